// round 1
// baseline (speedup 1.0000x reference)
#include <cuda_runtime.h>
#include <cuda_bf16.h>
#include <math.h>

// Problem constants
#define BB 2
#define SS 2048
#define DD 1024
#define HH 16
#define HD 64
#define BS (BB*SS)          // 4096 rows
#define D3 (3*DD)           // 3072

// ---------------- scratch (device globals; no allocation allowed) ------------
__device__ float g_xn [BS*DD];      // layernorm output
__device__ float g_qkv[BS*D3];      // fused qkv (rope applied in-place on q,k)
__device__ float g_qh [BS*DD];      // in-proj q
__device__ float g_kh [BS*DD];      // in-proj k
__device__ float g_vh [BS*DD];      // in-proj v
__device__ float g_att[BS*DD];      // attention output (b,s,h*64+dd)
__device__ float g_cos[SS*(DD/2)];  // rope tables
__device__ float g_sin[SS*(DD/2)];

// ---------------- LayerNorm: one block per row (1024 cols) -------------------
__global__ void __launch_bounds__(256) ln_kernel(const float* __restrict__ x,
                                                 const float* __restrict__ g,
                                                 const float* __restrict__ bta,
                                                 float* __restrict__ out) {
    int row = blockIdx.x;
    const float4* xr = (const float4*)(x + (size_t)row * DD);
    int t = threadIdx.x;                 // 256 threads, 4 floats each
    float4 v = xr[t];
    float s  = v.x + v.y + v.z + v.w;
    float sq = v.x*v.x + v.y*v.y + v.z*v.z + v.w*v.w;
    #pragma unroll
    for (int off = 16; off; off >>= 1) {
        s  += __shfl_xor_sync(0xffffffffu, s,  off);
        sq += __shfl_xor_sync(0xffffffffu, sq, off);
    }
    __shared__ float red[16];
    int warp = t >> 5, lane = t & 31;
    if (lane == 0) { red[warp] = s; red[8 + warp] = sq; }
    __syncthreads();
    float ts = 0.f, tsq = 0.f;
    #pragma unroll
    for (int w = 0; w < 8; w++) { ts += red[w]; tsq += red[8 + w]; }
    float mu  = ts * (1.0f / DD);
    float var = tsq * (1.0f / DD) - mu * mu;
    float rs  = rsqrtf(var + 1e-5f);
    int col = t * 4;
    float4 gg = *(const float4*)(g   + col);
    float4 bb = *(const float4*)(bta + col);
    float4 o;
    o.x = (v.x - mu) * rs * gg.x + bb.x;
    o.y = (v.y - mu) * rs * gg.y + bb.y;
    o.z = (v.z - mu) * rs * gg.z + bb.z;
    o.w = (v.w - mu) * rs * gg.w + bb.w;
    *(float4*)(out + (size_t)row * DD + col) = o;
}

// ---------------- RoPE tables: accurate mod-2pi reduction in fp64 ------------
__global__ void rope_table_kernel() {
    int idx = blockIdx.x * blockDim.x + threadIdx.x;
    if (idx >= SS * (DD/2)) return;
    int pos = idx >> 9;           // /512
    int i   = idx & 511;
    // inv_freq = 10000^(-2i/d)
    double invf = exp(-((double)(2 * i) / (double)DD) * log(10000.0));
    float  ang  = __fmul_rn((float)pos, (float)invf);   // fp32, matches reference
    double r    = (double)ang;
    const double TWO_PI = 6.283185307179586476925286766559;
    r -= TWO_PI * rint(r / TWO_PI);
    float rf = (float)r;
    g_cos[idx] = cosf(rf);
    g_sin[idx] = sinf(rf);
}

// ---------------- RoPE apply: in-place on q,k halves of g_qkv ----------------
__global__ void rope_apply_kernel() {
    int idx = blockIdx.x * blockDim.x + threadIdx.x;   // BS * 512 pairs
    if (idx >= BS * (DD/2)) return;
    int row = idx >> 9;
    int i   = idx & 511;
    int pos = row & (SS - 1);
    float c = g_cos[pos * 512 + i];
    float s = g_sin[pos * 512 + i];
    float2* qp = (float2*)&g_qkv[(size_t)row * D3 + 2 * i];
    float2* kp = (float2*)&g_qkv[(size_t)row * D3 + DD + 2 * i];
    float2 q = *qp, k = *kp;
    float2 qo, ko;
    qo.x = q.x * c - q.y * s;  qo.y = q.y * c + q.x * s;
    ko.x = k.x * c - k.y * s;  ko.y = k.y * c + k.x * s;
    *qp = qo;  *kp = ko;
}

// ---------------- SGEMM (NT): C[M,N] = A[M,K] * B[N,K]^T + bias[N] -----------
// 128x128 tile, BK=16, 256 threads, 8x8 per thread (two 4x4 float4 quads)
__global__ void __launch_bounds__(256) sgemm_nt(const float* __restrict__ A,
                                               const float* __restrict__ B,
                                               const float* __restrict__ bias,
                                               float* __restrict__ C,
                                               int M, int N, int K,
                                               int lda, int ldb, int ldc) {
    __shared__ float As[16][132];
    __shared__ float Bs[16][132];
    int bx = blockIdx.x, by = blockIdx.y;
    int tid = threadIdx.x;
    int tx = tid & 15, ty = tid >> 4;

    const float* Ab = A + (size_t)(by * 128) * lda;
    const float* Bb = B + (size_t)(bx * 128) * ldb;

    float acc[8][8];
    #pragma unroll
    for (int i = 0; i < 8; i++)
        #pragma unroll
        for (int j = 0; j < 8; j++) acc[i][j] = 0.f;

    for (int k0 = 0; k0 < K; k0 += 16) {
        #pragma unroll
        for (int i = 0; i < 2; i++) {
            int f4  = tid + i * 256;          // 0..511
            int row = f4 >> 2;                // 0..127
            int kk  = (f4 & 3) * 4;           // 0,4,8,12
            float4 a = *(const float4*)(Ab + (size_t)row * lda + k0 + kk);
            As[kk+0][row] = a.x; As[kk+1][row] = a.y;
            As[kk+2][row] = a.z; As[kk+3][row] = a.w;
            float4 b = *(const float4*)(Bb + (size_t)row * ldb + k0 + kk);
            Bs[kk+0][row] = b.x; Bs[kk+1][row] = b.y;
            Bs[kk+2][row] = b.z; Bs[kk+3][row] = b.w;
        }
        __syncthreads();
        #pragma unroll
        for (int k = 0; k < 16; k++) {
            float4 a0 = *(float4*)&As[k][ty * 4];
            float4 a1 = *(float4*)&As[k][64 + ty * 4];
            float4 b0 = *(float4*)&Bs[k][tx * 4];
            float4 b1 = *(float4*)&Bs[k][64 + tx * 4];
            float av[8] = {a0.x,a0.y,a0.z,a0.w,a1.x,a1.y,a1.z,a1.w};
            float bv[8] = {b0.x,b0.y,b0.z,b0.w,b1.x,b1.y,b1.z,b1.w};
            #pragma unroll
            for (int i = 0; i < 8; i++)
                #pragma unroll
                for (int j = 0; j < 8; j++)
                    acc[i][j] += av[i] * bv[j];
        }
        __syncthreads();
    }

    float4 bi0 = *(const float4*)(bias + bx * 128 + tx * 4);
    float4 bi1 = *(const float4*)(bias + bx * 128 + 64 + tx * 4);
    #pragma unroll
    for (int i = 0; i < 8; i++) {
        int m = by * 128 + ((i < 4) ? (ty * 4 + i) : (64 + ty * 4 + (i - 4)));
        float* crow = C + (size_t)m * ldc + bx * 128;
        float4 o0 = make_float4(acc[i][0] + bi0.x, acc[i][1] + bi0.y,
                                acc[i][2] + bi0.z, acc[i][3] + bi0.w);
        float4 o1 = make_float4(acc[i][4] + bi1.x, acc[i][5] + bi1.y,
                                acc[i][6] + bi1.z, acc[i][7] + bi1.w);
        *(float4*)(crow + tx * 4)      = o0;
        *(float4*)(crow + 64 + tx * 4) = o1;
    }
}

// ---------------- Flash-style attention: 64x64 tiles, online softmax ---------
// grid (S/64, H, B), 256 threads (16x16), each thread 4x4 of S/P and of O
#define LDT 68
#define ATT_SMEM (4 * 64 * LDT * 4)

__global__ void __launch_bounds__(256) attn_kernel(const float* __restrict__ mask) {
    extern __shared__ float sm[];
    float* Qst = sm;                 // [64][68] transposed: [k][qi]
    float* Kst = sm + 64 * LDT;      // [k][kj]
    float* Vsm = sm + 2 * 64 * LDT;  // [j][dd]
    float* Pst = sm + 3 * 64 * LDT;  // [j][qi]

    int q0 = blockIdx.x * 64;
    int h  = blockIdx.y;
    int b  = blockIdx.z;
    int tid = threadIdx.x;
    int tx = tid & 15, ty = tid >> 4;

    const float* qbase = g_qh + ((size_t)(b * SS + q0)) * DD + h * HD;
    const float* kbase = g_kh + ((size_t)b * SS) * DD + h * HD;
    const float* vbase = g_vh + ((size_t)b * SS) * DD + h * HD;
    const float* mbase = mask + ((size_t)(b * SS + q0)) * SS;

    for (int idx = tid; idx < 4096; idx += 256) {
        int qi = idx >> 6, k = idx & 63;
        Qst[k * LDT + qi] = qbase[(size_t)qi * DD + k];
    }

    float m_i[4], l_i[4], o[4][4];
    #pragma unroll
    for (int a = 0; a < 4; a++) {
        m_i[a] = -1e30f; l_i[a] = 0.f;
        #pragma unroll
        for (int j = 0; j < 4; j++) o[a][j] = 0.f;
    }

    for (int j0 = 0; j0 < SS; j0 += 64) {
        __syncthreads();   // protect Kst/Vsm/Pst from prior iteration readers
        for (int idx = tid; idx < 4096; idx += 256) {
            int r = idx >> 6, c = idx & 63;
            Kst[c * LDT + r] = kbase[(size_t)(j0 + r) * DD + c];
            Vsm[r * LDT + c] = vbase[(size_t)(j0 + r) * DD + c];
        }
        __syncthreads();

        float s[4][4];
        #pragma unroll
        for (int a = 0; a < 4; a++)
            #pragma unroll
            for (int j = 0; j < 4; j++) s[a][j] = 0.f;

        #pragma unroll 8
        for (int k = 0; k < 64; k++) {
            float4 aq = *(float4*)&Qst[k * LDT + ty * 4];
            float4 bk = *(float4*)&Kst[k * LDT + tx * 4];
            float av[4] = {aq.x, aq.y, aq.z, aq.w};
            float bv[4] = {bk.x, bk.y, bk.z, bk.w};
            #pragma unroll
            for (int a = 0; a < 4; a++)
                #pragma unroll
                for (int j = 0; j < 4; j++) s[a][j] += av[a] * bv[j];
        }

        const float scl = 0.125f;   // 1/sqrt(64)
        #pragma unroll
        for (int a = 0; a < 4; a++) {
            float4 mk = *(const float4*)&mbase[(size_t)(ty * 4 + a) * SS + j0 + tx * 4];
            s[a][0] = s[a][0] * scl + mk.x;
            s[a][1] = s[a][1] * scl + mk.y;
            s[a][2] = s[a][2] * scl + mk.z;
            s[a][3] = s[a][3] * scl + mk.w;
        }

        #pragma unroll
        for (int a = 0; a < 4; a++) {
            float mr = fmaxf(fmaxf(s[a][0], s[a][1]), fmaxf(s[a][2], s[a][3]));
            #pragma unroll
            for (int off = 8; off; off >>= 1)
                mr = fmaxf(mr, __shfl_xor_sync(0xffffffffu, mr, off));
            float mnew = fmaxf(m_i[a], mr);
            float corr = __expf(m_i[a] - mnew);
            float rs = 0.f;
            #pragma unroll
            for (int j = 0; j < 4; j++) {
                s[a][j] = __expf(s[a][j] - mnew);
                rs += s[a][j];
            }
            #pragma unroll
            for (int off = 8; off; off >>= 1)
                rs += __shfl_xor_sync(0xffffffffu, rs, off);
            l_i[a] = l_i[a] * corr + rs;
            m_i[a] = mnew;
            #pragma unroll
            for (int j = 0; j < 4; j++) o[a][j] *= corr;
        }

        // stage P transposed: Pst[j][qi]
        #pragma unroll
        for (int a = 0; a < 4; a++)
            #pragma unroll
            for (int j = 0; j < 4; j++)
                Pst[(tx * 4 + j) * LDT + (ty * 4 + a)] = s[a][j];
        __syncthreads();

        #pragma unroll 8
        for (int j = 0; j < 64; j++) {
            float4 pv = *(float4*)&Pst[j * LDT + ty * 4];
            float4 vv = *(float4*)&Vsm[j * LDT + tx * 4];
            float pa[4] = {pv.x, pv.y, pv.z, pv.w};
            float vb[4] = {vv.x, vv.y, vv.z, vv.w};
            #pragma unroll
            for (int a = 0; a < 4; a++)
                #pragma unroll
                for (int jj = 0; jj < 4; jj++)
                    o[a][jj] += pa[a] * vb[jj];
        }
    }

    float* obase = g_att + ((size_t)(b * SS + q0)) * DD + h * HD;
    #pragma unroll
    for (int a = 0; a < 4; a++) {
        float inv = 1.0f / l_i[a];
        float4 ov = make_float4(o[a][0]*inv, o[a][1]*inv, o[a][2]*inv, o[a][3]*inv);
        *(float4*)&obase[(size_t)(ty * 4 + a) * DD + tx * 4] = ov;
    }
}

// ---------------- launch ------------------------------------------------------
extern "C" void kernel_launch(void* const* d_in, const int* in_sizes, int n_in,
                              void* d_out, int out_size) {
    const float* x     = (const float*)d_in[0];
    const float* mask  = (const float*)d_in[1];
    const float* ln_g  = (const float*)d_in[2];
    const float* ln_b  = (const float*)d_in[3];
    const float* w_qkv = (const float*)d_in[4];
    const float* b_qkv = (const float*)d_in[5];
    const float* in_w  = (const float*)d_in[6];
    const float* in_b  = (const float*)d_in[7];
    const float* out_w = (const float*)d_in[8];
    const float* out_b = (const float*)d_in[9];

    float *xn, *qkv, *qh, *kh, *vh, *att;
    cudaGetSymbolAddress((void**)&xn,  g_xn);
    cudaGetSymbolAddress((void**)&qkv, g_qkv);
    cudaGetSymbolAddress((void**)&qh,  g_qh);
    cudaGetSymbolAddress((void**)&kh,  g_kh);
    cudaGetSymbolAddress((void**)&vh,  g_vh);
    cudaGetSymbolAddress((void**)&att, g_att);

    cudaFuncSetAttribute(attn_kernel,
                         cudaFuncAttributeMaxDynamicSharedMemorySize, ATT_SMEM);

    // 1. LayerNorm
    ln_kernel<<<BS, 256>>>(x, ln_g, ln_b, xn);
    // 2. RoPE tables (independent, cheap)
    rope_table_kernel<<<(SS * (DD/2) + 255) / 256, 256>>>();
    // 3. fused QKV projection: (4096,3072) = xn(4096,1024) * w_qkv^T
    sgemm_nt<<<dim3(D3/128, BS/128), 256>>>(xn, w_qkv, b_qkv, qkv,
                                            BS, D3, DD, DD, DD, D3);
    // 4. RoPE on q,k (in place)
    rope_apply_kernel<<<(BS * (DD/2) + 255) / 256, 256>>>();
    // 5. in-projections
    sgemm_nt<<<dim3(DD/128, BS/128), 256>>>(qkv,            in_w,              in_b,        qh,
                                            BS, DD, DD, D3, DD, DD);
    sgemm_nt<<<dim3(DD/128, BS/128), 256>>>(qkv + DD,       in_w + DD*DD,      in_b + DD,   kh,
                                            BS, DD, DD, D3, DD, DD);
    sgemm_nt<<<dim3(DD/128, BS/128), 256>>>(qkv + 2*DD,     in_w + 2*DD*DD,    in_b + 2*DD, vh,
                                            BS, DD, DD, D3, DD, DD);
    // 6. attention
    attn_kernel<<<dim3(SS/64, HH, BB), 256, ATT_SMEM>>>(mask);
    // 7. out-projection -> d_out
    sgemm_nt<<<dim3(DD/128, BS/128), 256>>>(att, out_w, out_b, (float*)d_out,
                                            BS, DD, DD, DD, DD, DD);
}

// round 2
// speedup vs baseline: 1.4606x; 1.4606x over previous
#include <cuda_runtime.h>
#include <cuda_bf16.h>
#include <math.h>
#include <stdint.h>

// Problem constants
#define BB 2
#define SS 2048
#define DD 1024
#define HH 16
#define HD 64
#define BS (BB*SS)          // 4096 rows
#define D3 (3*DD)           // 3072

// ---------------- scratch (device globals; no allocation allowed) ------------
__device__ float g_xn [BS*DD];      // layernorm output
__device__ float g_qkv[BS*D3];      // fused qkv (rope applied in-place on q,k)
__device__ float g_qh [BS*DD];      // in-proj q
__device__ float g_kh [BS*DD];      // in-proj k
__device__ float g_vh [BS*DD];      // in-proj v
__device__ float g_att[BS*DD];      // attention output
__device__ float g_cos[SS*(DD/2)];  // rope tables
__device__ float g_sin[SS*(DD/2)];

// ---------------- helpers ----------------------------------------------------
__device__ __forceinline__ float to_tf32(float x) {
    float r;
    asm("cvt.rna.tf32.f32 %0, %1;" : "=f"(r) : "f"(x));
    return r;
}

__device__ __forceinline__ void mma_tf32(float (&d)[4],
                                         const uint32_t (&a)[4],
                                         const uint32_t (&b)[2]) {
    asm volatile(
        "mma.sync.aligned.m16n8k8.row.col.f32.tf32.tf32.f32 "
        "{%0,%1,%2,%3}, {%4,%5,%6,%7}, {%8,%9}, {%0,%1,%2,%3};"
        : "+f"(d[0]), "+f"(d[1]), "+f"(d[2]), "+f"(d[3])
        : "r"(a[0]), "r"(a[1]), "r"(a[2]), "r"(a[3]),
          "r"(b[0]), "r"(b[1]));
}

// ---------------- LayerNorm: one block per row (1024 cols) -------------------
__global__ void __launch_bounds__(256) ln_kernel(const float* __restrict__ x,
                                                 const float* __restrict__ g,
                                                 const float* __restrict__ bta,
                                                 float* __restrict__ out) {
    int row = blockIdx.x;
    const float4* xr = (const float4*)(x + (size_t)row * DD);
    int t = threadIdx.x;
    float4 v = xr[t];
    float s  = v.x + v.y + v.z + v.w;
    float sq = v.x*v.x + v.y*v.y + v.z*v.z + v.w*v.w;
    #pragma unroll
    for (int off = 16; off; off >>= 1) {
        s  += __shfl_xor_sync(0xffffffffu, s,  off);
        sq += __shfl_xor_sync(0xffffffffu, sq, off);
    }
    __shared__ float red[16];
    int warp = t >> 5, lane = t & 31;
    if (lane == 0) { red[warp] = s; red[8 + warp] = sq; }
    __syncthreads();
    float ts = 0.f, tsq = 0.f;
    #pragma unroll
    for (int w = 0; w < 8; w++) { ts += red[w]; tsq += red[8 + w]; }
    float mu  = ts * (1.0f / DD);
    float var = tsq * (1.0f / DD) - mu * mu;
    float rs  = rsqrtf(var + 1e-5f);
    int col = t * 4;
    float4 gg = *(const float4*)(g   + col);
    float4 bb = *(const float4*)(bta + col);
    float4 o;
    o.x = (v.x - mu) * rs * gg.x + bb.x;
    o.y = (v.y - mu) * rs * gg.y + bb.y;
    o.z = (v.z - mu) * rs * gg.z + bb.z;
    o.w = (v.w - mu) * rs * gg.w + bb.w;
    *(float4*)(out + (size_t)row * DD + col) = o;
}

// ---------------- RoPE tables: accurate mod-2pi reduction in fp64 ------------
__global__ void rope_table_kernel() {
    int idx = blockIdx.x * blockDim.x + threadIdx.x;
    if (idx >= SS * (DD/2)) return;
    int pos = idx >> 9;
    int i   = idx & 511;
    double invf = exp(-((double)(2 * i) / (double)DD) * log(10000.0));
    float  ang  = __fmul_rn((float)pos, (float)invf);
    double r    = (double)ang;
    const double TWO_PI = 6.283185307179586476925286766559;
    r -= TWO_PI * rint(r / TWO_PI);
    float rf = (float)r;
    g_cos[idx] = cosf(rf);
    g_sin[idx] = sinf(rf);
}

// ---------------- RoPE apply: in-place on q,k halves of g_qkv ----------------
__global__ void rope_apply_kernel() {
    int idx = blockIdx.x * blockDim.x + threadIdx.x;
    if (idx >= BS * (DD/2)) return;
    int row = idx >> 9;
    int i   = idx & 511;
    int pos = row & (SS - 1);
    float c = g_cos[pos * 512 + i];
    float s = g_sin[pos * 512 + i];
    float2* qp = (float2*)&g_qkv[(size_t)row * D3 + 2 * i];
    float2* kp = (float2*)&g_qkv[(size_t)row * D3 + DD + 2 * i];
    float2 q = *qp, k = *kp;
    float2 qo, ko;
    qo.x = q.x * c - q.y * s;  qo.y = q.y * c + q.x * s;
    ko.x = k.x * c - k.y * s;  ko.y = k.y * c + k.x * s;
    *qp = qo;  *kp = ko;
}

// ---------------- TF32 tensor-core GEMM (NT): C = A[M,K]*B[N,K]^T + bias -----
// 128x128 block tile, BK=32, 256 threads = 8 warps (2 x 4), warp tile 64x32.
// Per warp: 4 m-tiles (m16) x 4 n-tiles (n8), mma.m16n8k8 tf32.
__global__ void __launch_bounds__(256, 2)
gemm_tf32(const float* __restrict__ A, const float* __restrict__ B,
          const float* __restrict__ bias, float* __restrict__ C,
          int K, int lda, int ldb, int ldc) {
    __shared__ float As[128][36];
    __shared__ float Bs[128][36];
    int tid  = threadIdx.x;
    int warp = tid >> 5, lane = tid & 31;
    int g = lane >> 2, t4 = lane & 3;
    int wm = (warp & 1) * 64;
    int wn = (warp >> 1) * 32;

    const float* Ab = A + (size_t)(blockIdx.y * 128) * lda;
    const float* Bb = B + (size_t)(blockIdx.x * 128) * ldb;

    float acc[4][4][4];
    #pragma unroll
    for (int mt = 0; mt < 4; mt++)
        #pragma unroll
        for (int nt = 0; nt < 4; nt++)
            #pragma unroll
            for (int r = 0; r < 4; r++) acc[mt][nt][r] = 0.f;

    for (int k0 = 0; k0 < K; k0 += 32) {
        #pragma unroll
        for (int i = 0; i < 4; i++) {
            int idx = tid + i * 256;          // 0..1023
            int row = idx >> 3;               // 0..127
            int kk  = (idx & 7) * 4;          // 0..28
            float4 a = *(const float4*)(Ab + (size_t)row * lda + k0 + kk);
            a.x = to_tf32(a.x); a.y = to_tf32(a.y);
            a.z = to_tf32(a.z); a.w = to_tf32(a.w);
            *(float4*)&As[row][kk] = a;
            float4 b = *(const float4*)(Bb + (size_t)row * ldb + k0 + kk);
            b.x = to_tf32(b.x); b.y = to_tf32(b.y);
            b.z = to_tf32(b.z); b.w = to_tf32(b.w);
            *(float4*)&Bs[row][kk] = b;
        }
        __syncthreads();

        #pragma unroll
        for (int ks = 0; ks < 4; ks++) {
            int k = ks * 8;
            uint32_t af[4][4], bf[4][2];
            #pragma unroll
            for (int mt = 0; mt < 4; mt++) {
                int r = wm + mt * 16 + g;
                af[mt][0] = __float_as_uint(As[r    ][k + t4    ]);
                af[mt][1] = __float_as_uint(As[r + 8][k + t4    ]);
                af[mt][2] = __float_as_uint(As[r    ][k + t4 + 4]);
                af[mt][3] = __float_as_uint(As[r + 8][k + t4 + 4]);
            }
            #pragma unroll
            for (int nt = 0; nt < 4; nt++) {
                int c = wn + nt * 8 + g;
                bf[nt][0] = __float_as_uint(Bs[c][k + t4    ]);
                bf[nt][1] = __float_as_uint(Bs[c][k + t4 + 4]);
            }
            #pragma unroll
            for (int mt = 0; mt < 4; mt++)
                #pragma unroll
                for (int nt = 0; nt < 4; nt++)
                    mma_tf32(acc[mt][nt], af[mt], bf[nt]);
        }
        __syncthreads();
    }

    // epilogue: c0 (g, 2*t4) c1 (g, 2*t4+1) c2 (g+8, 2*t4) c3 (g+8, 2*t4+1)
    #pragma unroll
    for (int mt = 0; mt < 4; mt++) {
        int row = blockIdx.y * 128 + wm + mt * 16 + g;
        #pragma unroll
        for (int nt = 0; nt < 4; nt++) {
            int col = blockIdx.x * 128 + wn + nt * 8 + 2 * t4;
            float b0 = bias[col], b1 = bias[col + 1];
            float2 o0 = make_float2(acc[mt][nt][0] + b0, acc[mt][nt][1] + b1);
            float2 o1 = make_float2(acc[mt][nt][2] + b0, acc[mt][nt][3] + b1);
            *(float2*)&C[(size_t)row * ldc + col]       = o0;
            *(float2*)&C[(size_t)(row + 8) * ldc + col] = o1;
        }
    }
}

// ---------------- Flash-style attention: 64x64 tiles, online softmax ---------
#define LDT 68
#define ATT_SMEM (4 * 64 * LDT * 4)

__global__ void __launch_bounds__(256) attn_kernel(const float* __restrict__ mask) {
    extern __shared__ float sm[];
    float* Qst = sm;                 // [k][qi]
    float* Kst = sm + 64 * LDT;      // [k][kj]
    float* Vsm = sm + 2 * 64 * LDT;  // [j][dd]
    float* Pst = sm + 3 * 64 * LDT;  // [j][qi]

    int q0 = blockIdx.x * 64;
    int h  = blockIdx.y;
    int b  = blockIdx.z;
    int tid = threadIdx.x;
    int tx = tid & 15, ty = tid >> 4;

    const float* qbase = g_qh + ((size_t)(b * SS + q0)) * DD + h * HD;
    const float* kbase = g_kh + ((size_t)b * SS) * DD + h * HD;
    const float* vbase = g_vh + ((size_t)b * SS) * DD + h * HD;
    const float* mbase = mask + ((size_t)(b * SS + q0)) * SS;

    for (int idx = tid; idx < 4096; idx += 256) {
        int qi = idx >> 6, k = idx & 63;
        Qst[k * LDT + qi] = qbase[(size_t)qi * DD + k];
    }

    float m_i[4], l_i[4], o[4][4];
    #pragma unroll
    for (int a = 0; a < 4; a++) {
        m_i[a] = -1e30f; l_i[a] = 0.f;
        #pragma unroll
        for (int j = 0; j < 4; j++) o[a][j] = 0.f;
    }

    for (int j0 = 0; j0 < SS; j0 += 64) {
        __syncthreads();
        for (int idx = tid; idx < 4096; idx += 256) {
            int r = idx >> 6, c = idx & 63;
            Kst[c * LDT + r] = kbase[(size_t)(j0 + r) * DD + c];
            Vsm[r * LDT + c] = vbase[(size_t)(j0 + r) * DD + c];
        }
        __syncthreads();

        float s[4][4];
        #pragma unroll
        for (int a = 0; a < 4; a++)
            #pragma unroll
            for (int j = 0; j < 4; j++) s[a][j] = 0.f;

        #pragma unroll 8
        for (int k = 0; k < 64; k++) {
            float4 aq = *(float4*)&Qst[k * LDT + ty * 4];
            float4 bk = *(float4*)&Kst[k * LDT + tx * 4];
            float av[4] = {aq.x, aq.y, aq.z, aq.w};
            float bv[4] = {bk.x, bk.y, bk.z, bk.w};
            #pragma unroll
            for (int a = 0; a < 4; a++)
                #pragma unroll
                for (int j = 0; j < 4; j++) s[a][j] += av[a] * bv[j];
        }

        const float scl = 0.125f;
        #pragma unroll
        for (int a = 0; a < 4; a++) {
            float4 mk = *(const float4*)&mbase[(size_t)(ty * 4 + a) * SS + j0 + tx * 4];
            s[a][0] = s[a][0] * scl + mk.x;
            s[a][1] = s[a][1] * scl + mk.y;
            s[a][2] = s[a][2] * scl + mk.z;
            s[a][3] = s[a][3] * scl + mk.w;
        }

        #pragma unroll
        for (int a = 0; a < 4; a++) {
            float mr = fmaxf(fmaxf(s[a][0], s[a][1]), fmaxf(s[a][2], s[a][3]));
            #pragma unroll
            for (int off = 8; off; off >>= 1)
                mr = fmaxf(mr, __shfl_xor_sync(0xffffffffu, mr, off));
            float mnew = fmaxf(m_i[a], mr);
            float corr = __expf(m_i[a] - mnew);
            float rs = 0.f;
            #pragma unroll
            for (int j = 0; j < 4; j++) {
                s[a][j] = __expf(s[a][j] - mnew);
                rs += s[a][j];
            }
            #pragma unroll
            for (int off = 8; off; off >>= 1)
                rs += __shfl_xor_sync(0xffffffffu, rs, off);
            l_i[a] = l_i[a] * corr + rs;
            m_i[a] = mnew;
            #pragma unroll
            for (int j = 0; j < 4; j++) o[a][j] *= corr;
        }

        #pragma unroll
        for (int a = 0; a < 4; a++)
            #pragma unroll
            for (int j = 0; j < 4; j++)
                Pst[(tx * 4 + j) * LDT + (ty * 4 + a)] = s[a][j];
        __syncthreads();

        #pragma unroll 8
        for (int j = 0; j < 64; j++) {
            float4 pv = *(float4*)&Pst[j * LDT + ty * 4];
            float4 vv = *(float4*)&Vsm[j * LDT + tx * 4];
            float pa[4] = {pv.x, pv.y, pv.z, pv.w};
            float vb[4] = {vv.x, vv.y, vv.z, vv.w};
            #pragma unroll
            for (int a = 0; a < 4; a++)
                #pragma unroll
                for (int jj = 0; jj < 4; jj++)
                    o[a][jj] += pa[a] * vb[jj];
        }
    }

    float* obase = g_att + ((size_t)(b * SS + q0)) * DD + h * HD;
    #pragma unroll
    for (int a = 0; a < 4; a++) {
        float inv = 1.0f / l_i[a];
        float4 ov = make_float4(o[a][0]*inv, o[a][1]*inv, o[a][2]*inv, o[a][3]*inv);
        *(float4*)&obase[(size_t)(ty * 4 + a) * DD + tx * 4] = ov;
    }
}

// ---------------- launch ------------------------------------------------------
extern "C" void kernel_launch(void* const* d_in, const int* in_sizes, int n_in,
                              void* d_out, int out_size) {
    const float* x     = (const float*)d_in[0];
    const float* mask  = (const float*)d_in[1];
    const float* ln_g  = (const float*)d_in[2];
    const float* ln_b  = (const float*)d_in[3];
    const float* w_qkv = (const float*)d_in[4];
    const float* b_qkv = (const float*)d_in[5];
    const float* in_w  = (const float*)d_in[6];
    const float* in_b  = (const float*)d_in[7];
    const float* out_w = (const float*)d_in[8];
    const float* out_b = (const float*)d_in[9];

    float *xn, *qkv, *qh, *kh, *vh, *att;
    cudaGetSymbolAddress((void**)&xn,  g_xn);
    cudaGetSymbolAddress((void**)&qkv, g_qkv);
    cudaGetSymbolAddress((void**)&qh,  g_qh);
    cudaGetSymbolAddress((void**)&kh,  g_kh);
    cudaGetSymbolAddress((void**)&vh,  g_vh);
    cudaGetSymbolAddress((void**)&att, g_att);

    cudaFuncSetAttribute(attn_kernel,
                         cudaFuncAttributeMaxDynamicSharedMemorySize, ATT_SMEM);

    // 1. LayerNorm
    ln_kernel<<<BS, 256>>>(x, ln_g, ln_b, xn);
    // 2. RoPE tables
    rope_table_kernel<<<(SS * (DD/2) + 255) / 256, 256>>>();
    // 3. fused QKV projection (4096 x 3072 x 1024)
    gemm_tf32<<<dim3(D3/128, BS/128), 256>>>(xn, w_qkv, b_qkv, qkv,
                                             DD, DD, DD, D3);
    // 4. RoPE on q,k (in place)
    rope_apply_kernel<<<(BS * (DD/2) + 255) / 256, 256>>>();
    // 5. in-projections (4096 x 1024 x 1024 each)
    gemm_tf32<<<dim3(DD/128, BS/128), 256>>>(qkv,        in_w,           in_b,        qh, DD, D3, DD, DD);
    gemm_tf32<<<dim3(DD/128, BS/128), 256>>>(qkv + DD,   in_w + DD*DD,   in_b + DD,   kh, DD, D3, DD, DD);
    gemm_tf32<<<dim3(DD/128, BS/128), 256>>>(qkv + 2*DD, in_w + 2*DD*DD, in_b + 2*DD, vh, DD, D3, DD, DD);
    // 6. attention
    attn_kernel<<<dim3(SS/64, HH, BB), 256, ATT_SMEM>>>(mask);
    // 7. out-projection -> d_out
    gemm_tf32<<<dim3(DD/128, BS/128), 256>>>(att, out_w, out_b, (float*)d_out,
                                             DD, DD, DD, DD);
}

// round 4
// speedup vs baseline: 1.6421x; 1.1243x over previous
#include <cuda_runtime.h>
#include <cuda_fp16.h>
#include <math.h>
#include <stdint.h>

// Problem constants
#define BB 2
#define SS 2048
#define DD 1024
#define HH 16
#define HD 64
#define BS (BB*SS)          // 4096 rows
#define D3 (3*DD)           // 3072

// ---------------- scratch (device globals; no allocation allowed) ------------
__device__ float g_xn [BS*DD];
__device__ float g_qkv[BS*D3];
__device__ float g_qh [BS*DD];
__device__ float g_kh [BS*DD];
__device__ float g_vh [BS*DD];
__device__ float g_att[BS*DD];
__device__ float g_cos[SS*(DD/2)];
__device__ float g_sin[SS*(DD/2)];

// ---------------- helpers ----------------------------------------------------
__device__ __forceinline__ void mma_fp16(float (&d)[4],
                                         const uint32_t (&a)[4],
                                         const uint32_t (&b)[2]) {
    asm volatile(
        "mma.sync.aligned.m16n8k16.row.col.f32.f16.f16.f32 "
        "{%0,%1,%2,%3}, {%4,%5,%6,%7}, {%8,%9}, {%0,%1,%2,%3};"
        : "+f"(d[0]), "+f"(d[1]), "+f"(d[2]), "+f"(d[3])
        : "r"(a[0]), "r"(a[1]), "r"(a[2]), "r"(a[3]),
          "r"(b[0]), "r"(b[1]));
}

__device__ __forceinline__ uint32_t pack_h2(float x, float y) {
    __half2 h;
    h.x = __float2half_rn(x);
    h.y = __float2half_rn(y);
    return *(uint32_t*)&h;
}

// ---------------- LayerNorm ---------------------------------------------------
__global__ void __launch_bounds__(256) ln_kernel(const float* __restrict__ x,
                                                 const float* __restrict__ g,
                                                 const float* __restrict__ bta,
                                                 float* __restrict__ out) {
    int row = blockIdx.x;
    const float4* xr = (const float4*)(x + (size_t)row * DD);
    int t = threadIdx.x;
    float4 v = xr[t];
    float s  = v.x + v.y + v.z + v.w;
    float sq = v.x*v.x + v.y*v.y + v.z*v.z + v.w*v.w;
    #pragma unroll
    for (int off = 16; off; off >>= 1) {
        s  += __shfl_xor_sync(0xffffffffu, s,  off);
        sq += __shfl_xor_sync(0xffffffffu, sq, off);
    }
    __shared__ float red[16];
    int warp = t >> 5, lane = t & 31;
    if (lane == 0) { red[warp] = s; red[8 + warp] = sq; }
    __syncthreads();
    float ts = 0.f, tsq = 0.f;
    #pragma unroll
    for (int w = 0; w < 8; w++) { ts += red[w]; tsq += red[8 + w]; }
    float mu  = ts * (1.0f / DD);
    float var = tsq * (1.0f / DD) - mu * mu;
    float rs  = rsqrtf(var + 1e-5f);
    int col = t * 4;
    float4 gg = *(const float4*)(g   + col);
    float4 bb = *(const float4*)(bta + col);
    float4 o;
    o.x = (v.x - mu) * rs * gg.x + bb.x;
    o.y = (v.y - mu) * rs * gg.y + bb.y;
    o.z = (v.z - mu) * rs * gg.z + bb.z;
    o.w = (v.w - mu) * rs * gg.w + bb.w;
    *(float4*)(out + (size_t)row * DD + col) = o;
}

// ---------------- RoPE tables -------------------------------------------------
__global__ void rope_table_kernel() {
    int idx = blockIdx.x * blockDim.x + threadIdx.x;
    if (idx >= SS * (DD/2)) return;
    int pos = idx >> 9;
    int i   = idx & 511;
    double invf = exp(-((double)(2 * i) / (double)DD) * log(10000.0));
    float  ang  = __fmul_rn((float)pos, (float)invf);
    double r    = (double)ang;
    const double TWO_PI = 6.283185307179586476925286766559;
    r -= TWO_PI * rint(r / TWO_PI);
    float rf = (float)r;
    g_cos[idx] = cosf(rf);
    g_sin[idx] = sinf(rf);
}

// ---------------- RoPE apply --------------------------------------------------
__global__ void rope_apply_kernel() {
    int idx = blockIdx.x * blockDim.x + threadIdx.x;
    if (idx >= BS * (DD/2)) return;
    int row = idx >> 9;
    int i   = idx & 511;
    int pos = row & (SS - 1);
    float c = g_cos[pos * 512 + i];
    float s = g_sin[pos * 512 + i];
    float2* qp = (float2*)&g_qkv[(size_t)row * D3 + 2 * i];
    float2* kp = (float2*)&g_qkv[(size_t)row * D3 + DD + 2 * i];
    float2 q = *qp, k = *kp;
    float2 qo, ko;
    qo.x = q.x * c - q.y * s;  qo.y = q.y * c + q.x * s;
    ko.x = k.x * c - k.y * s;  ko.y = k.y * c + k.x * s;
    *qp = qo;  *kp = ko;
}

// ---------------- FP16 tensor-core GEMM (NT): C = A[M,K]*B[N,K]^T + bias -----
// 128x128 block tile, BK=32, 256 threads = 8 warps (2 x 4), warp tile 64x32.
// Per warp: 4 m-tiles (m16) x 4 n-tiles (n8) x 2 k-steps, mma.m16n8k16 f16.f32.
__global__ void __launch_bounds__(256, 2)
gemm_fp16(const float* __restrict__ A, const float* __restrict__ B,
          const float* __restrict__ bias, float* __restrict__ C,
          int K, int lda, int ldb, int ldc) {
    __shared__ __half As[128][40];
    __shared__ __half Bs[128][40];
    int tid  = threadIdx.x;
    int warp = tid >> 5, lane = tid & 31;
    int g = lane >> 2, t4 = lane & 3;
    int wm = (warp & 1) * 64;
    int wn = (warp >> 1) * 32;

    const float* Ab = A + (size_t)(blockIdx.y * 128) * lda;
    const float* Bb = B + (size_t)(blockIdx.x * 128) * ldb;

    float acc[4][4][4];
    #pragma unroll
    for (int mt = 0; mt < 4; mt++)
        #pragma unroll
        for (int nt = 0; nt < 4; nt++)
            #pragma unroll
            for (int r = 0; r < 4; r++) acc[mt][nt][r] = 0.f;

    for (int k0 = 0; k0 < K; k0 += 32) {
        #pragma unroll
        for (int i = 0; i < 4; i++) {
            int idx = tid + i * 256;          // 0..1023
            int row = idx >> 3;               // 0..127
            int kk  = (idx & 7) * 4;          // 0..28
            float4 a = *(const float4*)(Ab + (size_t)row * lda + k0 + kk);
            *(uint2*)&As[row][kk] = make_uint2(pack_h2(a.x, a.y), pack_h2(a.z, a.w));
            float4 b = *(const float4*)(Bb + (size_t)row * ldb + k0 + kk);
            *(uint2*)&Bs[row][kk] = make_uint2(pack_h2(b.x, b.y), pack_h2(b.z, b.w));
        }
        __syncthreads();

        #pragma unroll
        for (int ks = 0; ks < 2; ks++) {
            int k = ks * 16;
            uint32_t af[4][4], bf[4][2];
            #pragma unroll
            for (int mt = 0; mt < 4; mt++) {
                int r = wm + mt * 16 + g;
                af[mt][0] = *(uint32_t*)&As[r    ][k + 2 * t4    ];
                af[mt][1] = *(uint32_t*)&As[r + 8][k + 2 * t4    ];
                af[mt][2] = *(uint32_t*)&As[r    ][k + 2 * t4 + 8];
                af[mt][3] = *(uint32_t*)&As[r + 8][k + 2 * t4 + 8];
            }
            #pragma unroll
            for (int nt = 0; nt < 4; nt++) {
                int c = wn + nt * 8 + g;
                bf[nt][0] = *(uint32_t*)&Bs[c][k + 2 * t4    ];
                bf[nt][1] = *(uint32_t*)&Bs[c][k + 2 * t4 + 8];
            }
            #pragma unroll
            for (int mt = 0; mt < 4; mt++)
                #pragma unroll
                for (int nt = 0; nt < 4; nt++)
                    mma_fp16(acc[mt][nt], af[mt], bf[nt]);
        }
        __syncthreads();
    }

    // epilogue: c0 (g, 2*t4) c1 (g, 2*t4+1) c2 (g+8, 2*t4) c3 (g+8, 2*t4+1)
    #pragma unroll
    for (int mt = 0; mt < 4; mt++) {
        int row = blockIdx.y * 128 + wm + mt * 16 + g;
        #pragma unroll
        for (int nt = 0; nt < 4; nt++) {
            int col = blockIdx.x * 128 + wn + nt * 8 + 2 * t4;
            float b0 = bias[col], b1 = bias[col + 1];
            float2 o0 = make_float2(acc[mt][nt][0] + b0, acc[mt][nt][1] + b1);
            float2 o1 = make_float2(acc[mt][nt][2] + b0, acc[mt][nt][3] + b1);
            *(float2*)&C[(size_t)row * ldc + col]       = o0;
            *(float2*)&C[(size_t)(row + 8) * ldc + col] = o1;
        }
    }
}

// ---------------- Flash-style attention (fp32 SIMT, verified) -----------------
#define LDT 68
#define ATT_SMEM (4 * 64 * LDT * 4)

__global__ void __launch_bounds__(256) attn_kernel(const float* __restrict__ mask) {
    extern __shared__ float sm[];
    float* Qst = sm;
    float* Kst = sm + 64 * LDT;
    float* Vsm = sm + 2 * 64 * LDT;
    float* Pst = sm + 3 * 64 * LDT;

    int q0 = blockIdx.x * 64;
    int h  = blockIdx.y;
    int b  = blockIdx.z;
    int tid = threadIdx.x;
    int tx = tid & 15, ty = tid >> 4;

    const float* qbase = g_qh + ((size_t)(b * SS + q0)) * DD + h * HD;
    const float* kbase = g_kh + ((size_t)b * SS) * DD + h * HD;
    const float* vbase = g_vh + ((size_t)b * SS) * DD + h * HD;
    const float* mbase = mask + ((size_t)(b * SS + q0)) * SS;

    for (int idx = tid; idx < 4096; idx += 256) {
        int qi = idx >> 6, k = idx & 63;
        Qst[k * LDT + qi] = qbase[(size_t)qi * DD + k];
    }

    float m_i[4], l_i[4], o[4][4];
    #pragma unroll
    for (int a = 0; a < 4; a++) {
        m_i[a] = -1e30f; l_i[a] = 0.f;
        #pragma unroll
        for (int j = 0; j < 4; j++) o[a][j] = 0.f;
    }

    for (int j0 = 0; j0 < SS; j0 += 64) {
        __syncthreads();
        for (int idx = tid; idx < 4096; idx += 256) {
            int r = idx >> 6, c = idx & 63;
            Kst[c * LDT + r] = kbase[(size_t)(j0 + r) * DD + c];
            Vsm[r * LDT + c] = vbase[(size_t)(j0 + r) * DD + c];
        }
        __syncthreads();

        float s[4][4];
        #pragma unroll
        for (int a = 0; a < 4; a++)
            #pragma unroll
            for (int j = 0; j < 4; j++) s[a][j] = 0.f;

        #pragma unroll 8
        for (int k = 0; k < 64; k++) {
            float4 aq = *(float4*)&Qst[k * LDT + ty * 4];
            float4 bk = *(float4*)&Kst[k * LDT + tx * 4];
            float av[4] = {aq.x, aq.y, aq.z, aq.w};
            float bv[4] = {bk.x, bk.y, bk.z, bk.w};
            #pragma unroll
            for (int a = 0; a < 4; a++)
                #pragma unroll
                for (int j = 0; j < 4; j++) s[a][j] += av[a] * bv[j];
        }

        const float scl = 0.125f;
        #pragma unroll
        for (int a = 0; a < 4; a++) {
            float4 mk = *(const float4*)&mbase[(size_t)(ty * 4 + a) * SS + j0 + tx * 4];
            s[a][0] = s[a][0] * scl + mk.x;
            s[a][1] = s[a][1] * scl + mk.y;
            s[a][2] = s[a][2] * scl + mk.z;
            s[a][3] = s[a][3] * scl + mk.w;
        }

        #pragma unroll
        for (int a = 0; a < 4; a++) {
            float mr = fmaxf(fmaxf(s[a][0], s[a][1]), fmaxf(s[a][2], s[a][3]));
            #pragma unroll
            for (int off = 8; off; off >>= 1)
                mr = fmaxf(mr, __shfl_xor_sync(0xffffffffu, mr, off));
            float mnew = fmaxf(m_i[a], mr);
            float corr = __expf(m_i[a] - mnew);
            float rs = 0.f;
            #pragma unroll
            for (int j = 0; j < 4; j++) {
                s[a][j] = __expf(s[a][j] - mnew);
                rs += s[a][j];
            }
            #pragma unroll
            for (int off = 8; off; off >>= 1)
                rs += __shfl_xor_sync(0xffffffffu, rs, off);
            l_i[a] = l_i[a] * corr + rs;
            m_i[a] = mnew;
            #pragma unroll
            for (int j = 0; j < 4; j++) o[a][j] *= corr;
        }

        #pragma unroll
        for (int a = 0; a < 4; a++)
            #pragma unroll
            for (int j = 0; j < 4; j++)
                Pst[(tx * 4 + j) * LDT + (ty * 4 + a)] = s[a][j];
        __syncthreads();

        #pragma unroll 8
        for (int j = 0; j < 64; j++) {
            float4 pv = *(float4*)&Pst[j * LDT + ty * 4];
            float4 vv = *(float4*)&Vsm[j * LDT + tx * 4];
            float pa[4] = {pv.x, pv.y, pv.z, pv.w};
            float vb[4] = {vv.x, vv.y, vv.z, vv.w};
            #pragma unroll
            for (int a = 0; a < 4; a++)
                #pragma unroll
                for (int jj = 0; jj < 4; jj++)
                    o[a][jj] += pa[a] * vb[jj];
        }
    }

    float* obase = g_att + ((size_t)(b * SS + q0)) * DD + h * HD;
    #pragma unroll
    for (int a = 0; a < 4; a++) {
        float inv = 1.0f / l_i[a];
        float4 ov = make_float4(o[a][0]*inv, o[a][1]*inv, o[a][2]*inv, o[a][3]*inv);
        *(float4*)&obase[(size_t)(ty * 4 + a) * DD + tx * 4] = ov;
    }
}

// ---------------- launch ------------------------------------------------------
extern "C" void kernel_launch(void* const* d_in, const int* in_sizes, int n_in,
                              void* d_out, int out_size) {
    const float* x     = (const float*)d_in[0];
    const float* mask  = (const float*)d_in[1];
    const float* ln_g  = (const float*)d_in[2];
    const float* ln_b  = (const float*)d_in[3];
    const float* w_qkv = (const float*)d_in[4];
    const float* b_qkv = (const float*)d_in[5];
    const float* in_w  = (const float*)d_in[6];
    const float* in_b  = (const float*)d_in[7];
    const float* out_w = (const float*)d_in[8];
    const float* out_b = (const float*)d_in[9];

    float *xn, *qkv, *qh, *kh, *vh, *att;
    cudaGetSymbolAddress((void**)&xn,  g_xn);
    cudaGetSymbolAddress((void**)&qkv, g_qkv);
    cudaGetSymbolAddress((void**)&qh,  g_qh);
    cudaGetSymbolAddress((void**)&kh,  g_kh);
    cudaGetSymbolAddress((void**)&vh,  g_vh);
    cudaGetSymbolAddress((void**)&att, g_att);

    cudaFuncSetAttribute(attn_kernel,
                         cudaFuncAttributeMaxDynamicSharedMemorySize, ATT_SMEM);

    // 1. LayerNorm
    ln_kernel<<<BS, 256>>>(x, ln_g, ln_b, xn);
    // 2. RoPE tables
    rope_table_kernel<<<(SS * (DD/2) + 255) / 256, 256>>>();
    // 3. fused QKV projection (4096 x 3072 x 1024)
    gemm_fp16<<<dim3(D3/128, BS/128), 256>>>(xn, w_qkv, b_qkv, qkv,
                                             DD, DD, DD, D3);
    // 4. RoPE on q,k (in place)
    rope_apply_kernel<<<(BS * (DD/2) + 255) / 256, 256>>>();
    // 5. in-projections (4096 x 1024 x 1024 each)
    gemm_fp16<<<dim3(DD/128, BS/128), 256>>>(qkv,        in_w,           in_b,        qh, DD, D3, DD, DD);
    gemm_fp16<<<dim3(DD/128, BS/128), 256>>>(qkv + DD,   in_w + DD*DD,   in_b + DD,   kh, DD, D3, DD, DD);
    gemm_fp16<<<dim3(DD/128, BS/128), 256>>>(qkv + 2*DD, in_w + 2*DD*DD, in_b + 2*DD, vh, DD, D3, DD, DD);
    // 6. attention (fp32 SIMT)
    attn_kernel<<<dim3(SS/64, HH, BB), 256, ATT_SMEM>>>(mask);
    // 7. out-projection -> d_out
    gemm_fp16<<<dim3(DD/128, BS/128), 256>>>(att, out_w, out_b, (float*)d_out,
                                             DD, DD, DD, DD);
}

// round 5
// speedup vs baseline: 1.8034x; 1.0982x over previous
#include <cuda_runtime.h>
#include <cuda_fp16.h>
#include <math.h>
#include <stdint.h>

// Problem constants
#define BB 2
#define SS 2048
#define DD 1024
#define HH 16
#define HD 64
#define BS (BB*SS)          // 4096 rows
#define D3 (3*DD)           // 3072

// ---------------- scratch (device globals; no allocation allowed) ------------
__device__ float  g_qkv [BS*D3];     // fp32 qkv (rope input)
__device__ float  g_qh  [BS*DD];     // fp32 in-proj outputs (attention inputs)
__device__ float  g_kh  [BS*DD];
__device__ float  g_vh  [BS*DD];
__device__ __half g_xnh [BS*DD];     // fp16 LN output (A of qkv GEMM)
__device__ __half g_qkvh[BS*D3];     // fp16 post-rope q,k + v (A of in-proj)
__device__ __half g_atth[BS*DD];     // fp16 attention out (A of out-proj)
__device__ __half g_wqkvh[D3*DD];    // fp16 weights
__device__ __half g_winh [D3*DD];
__device__ __half g_wouth[DD*DD];
__device__ float  g_cos[SS*(DD/2)];
__device__ float  g_sin[SS*(DD/2)];

// ---------------- ptx helpers -------------------------------------------------
__device__ __forceinline__ uint32_t smem_u32(const void* p) {
    uint32_t a;
    asm("{ .reg .u64 t; cvta.to.shared.u64 t, %1; cvt.u32.u64 %0, t; }"
        : "=r"(a) : "l"(p));
    return a;
}

__device__ __forceinline__ void cp16(uint32_t s, const void* g) {
    asm volatile("cp.async.cg.shared.global [%0], [%1], 16;" :: "r"(s), "l"(g));
}
__device__ __forceinline__ void cp_commit() {
    asm volatile("cp.async.commit_group;" ::: "memory");
}
template <int N>
__device__ __forceinline__ void cp_wait() {
    asm volatile("cp.async.wait_group %0;" :: "n"(N) : "memory");
}

#define LDSM4(r, addr) \
    asm volatile("ldmatrix.sync.aligned.m8n8.x4.shared.b16 {%0,%1,%2,%3}, [%4];" \
        : "=r"((r)[0]), "=r"((r)[1]), "=r"((r)[2]), "=r"((r)[3]) : "r"(addr))
#define LDSM2(r, addr) \
    asm volatile("ldmatrix.sync.aligned.m8n8.x2.shared.b16 {%0,%1}, [%2];" \
        : "=r"((r)[0]), "=r"((r)[1]) : "r"(addr))

__device__ __forceinline__ void mma_fp16(float (&d)[4],
                                         const uint32_t (&a)[4],
                                         const uint32_t (&b)[2]) {
    asm volatile(
        "mma.sync.aligned.m16n8k16.row.col.f32.f16.f16.f32 "
        "{%0,%1,%2,%3}, {%4,%5,%6,%7}, {%8,%9}, {%0,%1,%2,%3};"
        : "+f"(d[0]), "+f"(d[1]), "+f"(d[2]), "+f"(d[3])
        : "r"(a[0]), "r"(a[1]), "r"(a[2]), "r"(a[3]),
          "r"(b[0]), "r"(b[1]));
}

// ---------------- fp32 -> fp16 convert ---------------------------------------
__global__ void __launch_bounds__(256) f2h_kernel(const float* __restrict__ src,
                                                  __half* __restrict__ dst, int n4) {
    int i = blockIdx.x * blockDim.x + threadIdx.x;
    if (i >= n4) return;
    float4 v = ((const float4*)src)[i];
    __half2 h0 = __floats2half2_rn(v.x, v.y);
    __half2 h1 = __floats2half2_rn(v.z, v.w);
    *(uint2*)(dst + (size_t)i * 4) = make_uint2(*(uint32_t*)&h0, *(uint32_t*)&h1);
}

// ---------------- LayerNorm -> fp16 -------------------------------------------
__global__ void __launch_bounds__(256) ln_kernel(const float* __restrict__ x,
                                                 const float* __restrict__ g,
                                                 const float* __restrict__ bta,
                                                 __half* __restrict__ outh) {
    int row = blockIdx.x;
    const float4* xr = (const float4*)(x + (size_t)row * DD);
    int t = threadIdx.x;
    float4 v = xr[t];
    float s  = v.x + v.y + v.z + v.w;
    float sq = v.x*v.x + v.y*v.y + v.z*v.z + v.w*v.w;
    #pragma unroll
    for (int off = 16; off; off >>= 1) {
        s  += __shfl_xor_sync(0xffffffffu, s,  off);
        sq += __shfl_xor_sync(0xffffffffu, sq, off);
    }
    __shared__ float red[16];
    int warp = t >> 5, lane = t & 31;
    if (lane == 0) { red[warp] = s; red[8 + warp] = sq; }
    __syncthreads();
    float ts = 0.f, tsq = 0.f;
    #pragma unroll
    for (int w = 0; w < 8; w++) { ts += red[w]; tsq += red[8 + w]; }
    float mu  = ts * (1.0f / DD);
    float var = tsq * (1.0f / DD) - mu * mu;
    float rs  = rsqrtf(var + 1e-5f);
    int col = t * 4;
    float4 gg = *(const float4*)(g   + col);
    float4 bb = *(const float4*)(bta + col);
    __half2 h0 = __floats2half2_rn((v.x - mu) * rs * gg.x + bb.x,
                                   (v.y - mu) * rs * gg.y + bb.y);
    __half2 h1 = __floats2half2_rn((v.z - mu) * rs * gg.z + bb.z,
                                   (v.w - mu) * rs * gg.w + bb.w);
    *(uint2*)(outh + (size_t)row * DD + col) = make_uint2(*(uint32_t*)&h0, *(uint32_t*)&h1);
}

// ---------------- RoPE tables -------------------------------------------------
__global__ void rope_table_kernel() {
    int idx = blockIdx.x * blockDim.x + threadIdx.x;
    if (idx >= SS * (DD/2)) return;
    int pos = idx >> 9;
    int i   = idx & 511;
    double invf = exp(-((double)(2 * i) / (double)DD) * log(10000.0));
    float  ang  = __fmul_rn((float)pos, (float)invf);
    double r    = (double)ang;
    const double TWO_PI = 6.283185307179586476925286766559;
    r -= TWO_PI * rint(r / TWO_PI);
    float rf = (float)r;
    g_cos[idx] = cosf(rf);
    g_sin[idx] = sinf(rf);
}

// ---------------- RoPE apply: fp32 qkv -> fp16 q,k (rotated) + v --------------
__global__ void rope_apply_kernel() {
    int idx = blockIdx.x * blockDim.x + threadIdx.x;
    if (idx >= BS * (DD/2)) return;
    int row = idx >> 9;
    int i   = idx & 511;
    int pos = row & (SS - 1);
    float c = g_cos[pos * 512 + i];
    float s = g_sin[pos * 512 + i];
    size_t base = (size_t)row * D3 + 2 * i;
    float2 q = *(float2*)&g_qkv[base];
    float2 k = *(float2*)&g_qkv[base + DD];
    float2 v = *(float2*)&g_qkv[base + 2 * DD];
    __half2 qo = __floats2half2_rn(q.x * c - q.y * s, q.y * c + q.x * s);
    __half2 ko = __floats2half2_rn(k.x * c - k.y * s, k.y * c + k.x * s);
    __half2 vo = __floats2half2_rn(v.x, v.y);
    *(uint32_t*)&g_qkvh[base]          = *(uint32_t*)&qo;
    *(uint32_t*)&g_qkvh[base + DD]     = *(uint32_t*)&ko;
    *(uint32_t*)&g_qkvh[base + 2 * DD] = *(uint32_t*)&vo;
}

// ---------------- pipelined HGEMM (NT): C = A[M,K]*B[N,K]^T + bias ------------
// fp16 A,B; fp32 C. 128x128 tile, BK=32, 3-stage cp.async, ldmatrix fragments.
// 8 warps (2 x 4): warp tile 64x32 -> 4 m-tiles x 4 n-tiles of m16n8k16.
#define GH_ROWB   80                         // bytes per smem row (40 halfs)
#define GH_TILE   (128 * GH_ROWB)            // 10240 B per operand per stage
#define GH_STAGE  (2 * GH_TILE)              // 20480
#define GH_SMEM   (3 * GH_STAGE)             // 61440

__global__ void __launch_bounds__(256, 2)
gemm_h(const __half* __restrict__ A, const __half* __restrict__ B,
       const float* __restrict__ bias, float* __restrict__ C,
       int K, int lda, int ldb, int ldc) {
    extern __shared__ __align__(16) char gsm[];
    uint32_t sbase = smem_u32(gsm);
    int tid = threadIdx.x, warp = tid >> 5, lane = tid & 31;
    int g = lane >> 2, t4 = lane & 3;
    int wm = (warp & 1) * 64;
    int wn = (warp >> 1) * 32;

    const __half* Ab = A + (size_t)(blockIdx.y * 128) * lda;
    const __half* Bb = B + (size_t)(blockIdx.x * 128) * ldb;

    // per-thread cp.async coords (2 chunks of 16B per operand per stage)
    int c1 = tid + 256;
    int ar0 = tid >> 2, ak0 = (tid & 3) * 8;
    int ar1 = c1  >> 2, ak1 = (c1  & 3) * 8;

    // ldmatrix lane offsets (bytes within a stage)
    uint32_t aOff[4], bOff[4];
    #pragma unroll
    for (int mt = 0; mt < 4; mt++)
        aOff[mt] = (uint32_t)((wm + mt * 16 + (lane & 15)) * GH_ROWB + (lane >> 4) * 16);
    #pragma unroll
    for (int nt = 0; nt < 4; nt++)
        bOff[nt] = (uint32_t)((wn + nt * 8 + (lane & 7)) * GH_ROWB + ((lane >> 3) & 1) * 16)
                 + GH_TILE;

    float acc[4][4][4];
    #pragma unroll
    for (int mt = 0; mt < 4; mt++)
        #pragma unroll
        for (int nt = 0; nt < 4; nt++)
            #pragma unroll
            for (int r = 0; r < 4; r++) acc[mt][nt][r] = 0.f;

    int nk = K >> 5;

    // prologue: stages 0,1
    #pragma unroll
    for (int p = 0; p < 2; p++) {
        int k0 = p * 32;
        uint32_t st = sbase + p * GH_STAGE;
        cp16(st + ar0 * GH_ROWB + ak0 * 2,           Ab + (size_t)ar0 * lda + k0 + ak0);
        cp16(st + ar1 * GH_ROWB + ak1 * 2,           Ab + (size_t)ar1 * lda + k0 + ak1);
        cp16(st + GH_TILE + ar0 * GH_ROWB + ak0 * 2, Bb + (size_t)ar0 * ldb + k0 + ak0);
        cp16(st + GH_TILE + ar1 * GH_ROWB + ak1 * 2, Bb + (size_t)ar1 * ldb + k0 + ak1);
        cp_commit();
    }

    for (int it = 0; it < nk; it++) {
        cp_wait<1>();
        __syncthreads();

        if (it + 2 < nk) {
            int k0 = (it + 2) * 32;
            uint32_t st = sbase + ((it + 2) % 3) * GH_STAGE;
            cp16(st + ar0 * GH_ROWB + ak0 * 2,           Ab + (size_t)ar0 * lda + k0 + ak0);
            cp16(st + ar1 * GH_ROWB + ak1 * 2,           Ab + (size_t)ar1 * lda + k0 + ak1);
            cp16(st + GH_TILE + ar0 * GH_ROWB + ak0 * 2, Bb + (size_t)ar0 * ldb + k0 + ak0);
            cp16(st + GH_TILE + ar1 * GH_ROWB + ak1 * 2, Bb + (size_t)ar1 * ldb + k0 + ak1);
        }
        cp_commit();

        uint32_t sa = sbase + (it % 3) * GH_STAGE;
        #pragma unroll
        for (int ks = 0; ks < 2; ks++) {
            uint32_t af[4][4], bf[4][2];
            #pragma unroll
            for (int mt = 0; mt < 4; mt++) LDSM4(af[mt], sa + aOff[mt] + ks * 32);
            #pragma unroll
            for (int nt = 0; nt < 4; nt++) LDSM2(bf[nt], sa + bOff[nt] + ks * 32);
            #pragma unroll
            for (int mt = 0; mt < 4; mt++)
                #pragma unroll
                for (int nt = 0; nt < 4; nt++)
                    mma_fp16(acc[mt][nt], af[mt], bf[nt]);
        }
    }

    // epilogue: c0 (g, 2t4) c1 (g, 2t4+1) c2 (g+8, 2t4) c3 (g+8, 2t4+1)
    #pragma unroll
    for (int mt = 0; mt < 4; mt++) {
        int row = blockIdx.y * 128 + wm + mt * 16 + g;
        #pragma unroll
        for (int nt = 0; nt < 4; nt++) {
            int col = blockIdx.x * 128 + wn + nt * 8 + 2 * t4;
            float b0 = bias[col], b1 = bias[col + 1];
            float2 o0 = make_float2(acc[mt][nt][0] + b0, acc[mt][nt][1] + b1);
            float2 o1 = make_float2(acc[mt][nt][2] + b0, acc[mt][nt][3] + b1);
            *(float2*)&C[(size_t)row * ldc + col]       = o0;
            *(float2*)&C[(size_t)(row + 8) * ldc + col] = o1;
        }
    }
}

// ---------------- Flash-style attention (fp32 SIMT) -> fp16 out ---------------
#define LDT 68
#define ATT_SMEM (4 * 64 * LDT * 4)

__global__ void __launch_bounds__(256) attn_kernel(const float* __restrict__ mask) {
    extern __shared__ float sm[];
    float* Qst = sm;
    float* Kst = sm + 64 * LDT;
    float* Vsm = sm + 2 * 64 * LDT;
    float* Pst = sm + 3 * 64 * LDT;

    int q0 = blockIdx.x * 64;
    int h  = blockIdx.y;
    int b  = blockIdx.z;
    int tid = threadIdx.x;
    int tx = tid & 15, ty = tid >> 4;

    const float* qbase = g_qh + ((size_t)(b * SS + q0)) * DD + h * HD;
    const float* kbase = g_kh + ((size_t)b * SS) * DD + h * HD;
    const float* vbase = g_vh + ((size_t)b * SS) * DD + h * HD;
    const float* mbase = mask + ((size_t)(b * SS + q0)) * SS;

    for (int idx = tid; idx < 4096; idx += 256) {
        int qi = idx >> 6, k = idx & 63;
        Qst[k * LDT + qi] = qbase[(size_t)qi * DD + k];
    }

    float m_i[4], l_i[4], o[4][4];
    #pragma unroll
    for (int a = 0; a < 4; a++) {
        m_i[a] = -1e30f; l_i[a] = 0.f;
        #pragma unroll
        for (int j = 0; j < 4; j++) o[a][j] = 0.f;
    }

    for (int j0 = 0; j0 < SS; j0 += 64) {
        __syncthreads();
        for (int idx = tid; idx < 4096; idx += 256) {
            int r = idx >> 6, c = idx & 63;
            Kst[c * LDT + r] = kbase[(size_t)(j0 + r) * DD + c];
            Vsm[r * LDT + c] = vbase[(size_t)(j0 + r) * DD + c];
        }
        __syncthreads();

        float s[4][4];
        #pragma unroll
        for (int a = 0; a < 4; a++)
            #pragma unroll
            for (int j = 0; j < 4; j++) s[a][j] = 0.f;

        #pragma unroll 8
        for (int k = 0; k < 64; k++) {
            float4 aq = *(float4*)&Qst[k * LDT + ty * 4];
            float4 bk = *(float4*)&Kst[k * LDT + tx * 4];
            float av[4] = {aq.x, aq.y, aq.z, aq.w};
            float bv[4] = {bk.x, bk.y, bk.z, bk.w};
            #pragma unroll
            for (int a = 0; a < 4; a++)
                #pragma unroll
                for (int j = 0; j < 4; j++) s[a][j] += av[a] * bv[j];
        }

        const float scl = 0.125f;
        #pragma unroll
        for (int a = 0; a < 4; a++) {
            float4 mk = *(const float4*)&mbase[(size_t)(ty * 4 + a) * SS + j0 + tx * 4];
            s[a][0] = s[a][0] * scl + mk.x;
            s[a][1] = s[a][1] * scl + mk.y;
            s[a][2] = s[a][2] * scl + mk.z;
            s[a][3] = s[a][3] * scl + mk.w;
        }

        #pragma unroll
        for (int a = 0; a < 4; a++) {
            float mr = fmaxf(fmaxf(s[a][0], s[a][1]), fmaxf(s[a][2], s[a][3]));
            #pragma unroll
            for (int off = 8; off; off >>= 1)
                mr = fmaxf(mr, __shfl_xor_sync(0xffffffffu, mr, off));
            float mnew = fmaxf(m_i[a], mr);
            float corr = __expf(m_i[a] - mnew);
            float rs = 0.f;
            #pragma unroll
            for (int j = 0; j < 4; j++) {
                s[a][j] = __expf(s[a][j] - mnew);
                rs += s[a][j];
            }
            #pragma unroll
            for (int off = 8; off; off >>= 1)
                rs += __shfl_xor_sync(0xffffffffu, rs, off);
            l_i[a] = l_i[a] * corr + rs;
            m_i[a] = mnew;
            #pragma unroll
            for (int j = 0; j < 4; j++) o[a][j] *= corr;
        }

        #pragma unroll
        for (int a = 0; a < 4; a++)
            #pragma unroll
            for (int j = 0; j < 4; j++)
                Pst[(tx * 4 + j) * LDT + (ty * 4 + a)] = s[a][j];
        __syncthreads();

        #pragma unroll 8
        for (int j = 0; j < 64; j++) {
            float4 pv = *(float4*)&Pst[j * LDT + ty * 4];
            float4 vv = *(float4*)&Vsm[j * LDT + tx * 4];
            float pa[4] = {pv.x, pv.y, pv.z, pv.w};
            float vb[4] = {vv.x, vv.y, vv.z, vv.w};
            #pragma unroll
            for (int a = 0; a < 4; a++)
                #pragma unroll
                for (int jj = 0; jj < 4; jj++)
                    o[a][jj] += pa[a] * vb[jj];
        }
    }

    __half* obase = g_atth + ((size_t)(b * SS + q0)) * DD + h * HD;
    #pragma unroll
    for (int a = 0; a < 4; a++) {
        float inv = 1.0f / l_i[a];
        __half2 h0 = __floats2half2_rn(o[a][0] * inv, o[a][1] * inv);
        __half2 h1 = __floats2half2_rn(o[a][2] * inv, o[a][3] * inv);
        *(uint2*)&obase[(size_t)(ty * 4 + a) * DD + tx * 4] =
            make_uint2(*(uint32_t*)&h0, *(uint32_t*)&h1);
    }
}

// ---------------- launch ------------------------------------------------------
extern "C" void kernel_launch(void* const* d_in, const int* in_sizes, int n_in,
                              void* d_out, int out_size) {
    const float* x     = (const float*)d_in[0];
    const float* mask  = (const float*)d_in[1];
    const float* ln_g  = (const float*)d_in[2];
    const float* ln_b  = (const float*)d_in[3];
    const float* w_qkv = (const float*)d_in[4];
    const float* b_qkv = (const float*)d_in[5];
    const float* in_w  = (const float*)d_in[6];
    const float* in_b  = (const float*)d_in[7];
    const float* out_w = (const float*)d_in[8];
    const float* out_b = (const float*)d_in[9];

    float *qkv, *qh, *kh, *vh;
    __half *xnh, *qkvh, *atth, *wqkvh, *winh, *wouth;
    cudaGetSymbolAddress((void**)&qkv,   g_qkv);
    cudaGetSymbolAddress((void**)&qh,    g_qh);
    cudaGetSymbolAddress((void**)&kh,    g_kh);
    cudaGetSymbolAddress((void**)&vh,    g_vh);
    cudaGetSymbolAddress((void**)&xnh,   g_xnh);
    cudaGetSymbolAddress((void**)&qkvh,  g_qkvh);
    cudaGetSymbolAddress((void**)&atth,  g_atth);
    cudaGetSymbolAddress((void**)&wqkvh, g_wqkvh);
    cudaGetSymbolAddress((void**)&winh,  g_winh);
    cudaGetSymbolAddress((void**)&wouth, g_wouth);

    cudaFuncSetAttribute(attn_kernel,
                         cudaFuncAttributeMaxDynamicSharedMemorySize, ATT_SMEM);
    cudaFuncSetAttribute(gemm_h,
                         cudaFuncAttributeMaxDynamicSharedMemorySize, GH_SMEM);

    // 0. weight conversions (fp32 -> fp16, once per launch)
    f2h_kernel<<<(D3*DD/4 + 255)/256, 256>>>(w_qkv, wqkvh, D3*DD/4);
    f2h_kernel<<<(D3*DD/4 + 255)/256, 256>>>(in_w,  winh,  D3*DD/4);
    f2h_kernel<<<(DD*DD/4 + 255)/256, 256>>>(out_w, wouth, DD*DD/4);
    // 1. LayerNorm -> fp16
    ln_kernel<<<BS, 256>>>(x, ln_g, ln_b, xnh);
    // 2. RoPE tables
    rope_table_kernel<<<(SS * (DD/2) + 255) / 256, 256>>>();
    // 3. fused QKV projection (fp16 in, fp32 out)
    gemm_h<<<dim3(D3/128, BS/128), 256, GH_SMEM>>>(xnh, wqkvh, b_qkv, qkv,
                                                   DD, DD, DD, D3);
    // 4. RoPE -> fp16 q,k,v
    rope_apply_kernel<<<(BS * (DD/2) + 255) / 256, 256>>>();
    // 5. in-projections
    gemm_h<<<dim3(DD/128, BS/128), 256, GH_SMEM>>>(qkvh,        winh,           in_b,        qh, DD, D3, DD, DD);
    gemm_h<<<dim3(DD/128, BS/128), 256, GH_SMEM>>>(qkvh + DD,   winh + DD*DD,   in_b + DD,   kh, DD, D3, DD, DD);
    gemm_h<<<dim3(DD/128, BS/128), 256, GH_SMEM>>>(qkvh + 2*DD, winh + 2*DD*DD, in_b + 2*DD, vh, DD, D3, DD, DD);
    // 6. attention (fp32 SIMT) -> fp16 out
    attn_kernel<<<dim3(SS/64, HH, BB), 256, ATT_SMEM>>>(mask);
    // 7. out-projection -> d_out (fp32)
    gemm_h<<<dim3(DD/128, BS/128), 256, GH_SMEM>>>(atth, wouth, out_b, (float*)d_out,
                                                   DD, DD, DD, DD);
}

// round 6
// speedup vs baseline: 2.3010x; 1.2759x over previous
#include <cuda_runtime.h>
#include <cuda_fp16.h>
#include <math.h>
#include <stdint.h>

// Problem constants
#define BB 2
#define SS 2048
#define DD 1024
#define HH 16
#define HD 64
#define BS (BB*SS)          // 4096 rows
#define D3 (3*DD)           // 3072

// ---------------- scratch (device globals; no allocation allowed) ------------
__device__ float  g_qkv [BS*D3];     // fp32 qkv (rope input)
__device__ float  g_qh  [BS*DD];     // fp32 in-proj outputs (attention inputs)
__device__ float  g_kh  [BS*DD];
__device__ float  g_vh  [BS*DD];
__device__ __half g_xnh [BS*DD];     // fp16 LN output (A of qkv GEMM)
__device__ __half g_qkvh[BS*D3];     // fp16 post-rope q,k + v (A of in-proj)
__device__ __half g_atth[BS*DD];     // fp16 attention out (A of out-proj)
__device__ __half g_wqkvh[D3*DD];    // fp16 weights
__device__ __half g_winh [D3*DD];
__device__ __half g_wouth[DD*DD];
__device__ float  g_cos[SS*(DD/2)];
__device__ float  g_sin[SS*(DD/2)];

// ---------------- ptx helpers -------------------------------------------------
__device__ __forceinline__ uint32_t smem_u32(const void* p) {
    uint32_t a;
    asm("{ .reg .u64 t; cvta.to.shared.u64 t, %1; cvt.u32.u64 %0, t; }"
        : "=r"(a) : "l"(p));
    return a;
}

__device__ __forceinline__ void cp16(uint32_t s, const void* g) {
    asm volatile("cp.async.cg.shared.global [%0], [%1], 16;" :: "r"(s), "l"(g));
}
__device__ __forceinline__ void cp_commit() {
    asm volatile("cp.async.commit_group;" ::: "memory");
}
template <int N>
__device__ __forceinline__ void cp_wait() {
    asm volatile("cp.async.wait_group %0;" :: "n"(N) : "memory");
}

#define LDSM4(r, addr) \
    asm volatile("ldmatrix.sync.aligned.m8n8.x4.shared.b16 {%0,%1,%2,%3}, [%4];" \
        : "=r"((r)[0]), "=r"((r)[1]), "=r"((r)[2]), "=r"((r)[3]) : "r"(addr))
#define LDSM2(r, addr) \
    asm volatile("ldmatrix.sync.aligned.m8n8.x2.shared.b16 {%0,%1}, [%2];" \
        : "=r"((r)[0]), "=r"((r)[1]) : "r"(addr))
#define LDSM2T(r, addr) \
    asm volatile("ldmatrix.sync.aligned.m8n8.x2.trans.shared.b16 {%0,%1}, [%2];" \
        : "=r"((r)[0]), "=r"((r)[1]) : "r"(addr))

__device__ __forceinline__ void mma_fp16(float (&d)[4],
                                         const uint32_t (&a)[4],
                                         const uint32_t (&b)[2]) {
    asm volatile(
        "mma.sync.aligned.m16n8k16.row.col.f32.f16.f16.f32 "
        "{%0,%1,%2,%3}, {%4,%5,%6,%7}, {%8,%9}, {%0,%1,%2,%3};"
        : "+f"(d[0]), "+f"(d[1]), "+f"(d[2]), "+f"(d[3])
        : "r"(a[0]), "r"(a[1]), "r"(a[2]), "r"(a[3]),
          "r"(b[0]), "r"(b[1]));
}

__device__ __forceinline__ uint32_t pack_h2(float x, float y) {
    __half2 h;
    h.x = __float2half_rn(x);
    h.y = __float2half_rn(y);
    return *(uint32_t*)&h;
}

// split fp32 -> (hi, lo) fp16 pair packs for 2 consecutive values
__device__ __forceinline__ void split2(float2 v, uint32_t& hi, uint32_t& lo) {
    __half hx = __float2half_rn(v.x);
    __half hy = __float2half_rn(v.y);
    __half lx = __float2half_rn(v.x - __half2float(hx));
    __half ly = __float2half_rn(v.y - __half2float(hy));
    __half2 h; h.x = hx; h.y = hy;
    __half2 l; l.x = lx; l.y = ly;
    hi = *(uint32_t*)&h;
    lo = *(uint32_t*)&l;
}

// ---------------- fp32 -> fp16 convert ---------------------------------------
__global__ void __launch_bounds__(256) f2h_kernel(const float* __restrict__ src,
                                                  __half* __restrict__ dst, int n4) {
    int i = blockIdx.x * blockDim.x + threadIdx.x;
    if (i >= n4) return;
    float4 v = ((const float4*)src)[i];
    __half2 h0 = __floats2half2_rn(v.x, v.y);
    __half2 h1 = __floats2half2_rn(v.z, v.w);
    *(uint2*)(dst + (size_t)i * 4) = make_uint2(*(uint32_t*)&h0, *(uint32_t*)&h1);
}

// ---------------- LayerNorm -> fp16 -------------------------------------------
__global__ void __launch_bounds__(256) ln_kernel(const float* __restrict__ x,
                                                 const float* __restrict__ g,
                                                 const float* __restrict__ bta,
                                                 __half* __restrict__ outh) {
    int row = blockIdx.x;
    const float4* xr = (const float4*)(x + (size_t)row * DD);
    int t = threadIdx.x;
    float4 v = xr[t];
    float s  = v.x + v.y + v.z + v.w;
    float sq = v.x*v.x + v.y*v.y + v.z*v.z + v.w*v.w;
    #pragma unroll
    for (int off = 16; off; off >>= 1) {
        s  += __shfl_xor_sync(0xffffffffu, s,  off);
        sq += __shfl_xor_sync(0xffffffffu, sq, off);
    }
    __shared__ float red[16];
    int warp = t >> 5, lane = t & 31;
    if (lane == 0) { red[warp] = s; red[8 + warp] = sq; }
    __syncthreads();
    float ts = 0.f, tsq = 0.f;
    #pragma unroll
    for (int w = 0; w < 8; w++) { ts += red[w]; tsq += red[8 + w]; }
    float mu  = ts * (1.0f / DD);
    float var = tsq * (1.0f / DD) - mu * mu;
    float rs  = rsqrtf(var + 1e-5f);
    int col = t * 4;
    float4 gg = *(const float4*)(g   + col);
    float4 bb = *(const float4*)(bta + col);
    __half2 h0 = __floats2half2_rn((v.x - mu) * rs * gg.x + bb.x,
                                   (v.y - mu) * rs * gg.y + bb.y);
    __half2 h1 = __floats2half2_rn((v.z - mu) * rs * gg.z + bb.z,
                                   (v.w - mu) * rs * gg.w + bb.w);
    *(uint2*)(outh + (size_t)row * DD + col) = make_uint2(*(uint32_t*)&h0, *(uint32_t*)&h1);
}

// ---------------- RoPE tables -------------------------------------------------
__global__ void rope_table_kernel() {
    int idx = blockIdx.x * blockDim.x + threadIdx.x;
    if (idx >= SS * (DD/2)) return;
    int pos = idx >> 9;
    int i   = idx & 511;
    double invf = exp(-((double)(2 * i) / (double)DD) * log(10000.0));
    float  ang  = __fmul_rn((float)pos, (float)invf);
    double r    = (double)ang;
    const double TWO_PI = 6.283185307179586476925286766559;
    r -= TWO_PI * rint(r / TWO_PI);
    float rf = (float)r;
    g_cos[idx] = cosf(rf);
    g_sin[idx] = sinf(rf);
}

// ---------------- RoPE apply: fp32 qkv -> fp16 q,k (rotated) + v --------------
__global__ void rope_apply_kernel() {
    int idx = blockIdx.x * blockDim.x + threadIdx.x;
    if (idx >= BS * (DD/2)) return;
    int row = idx >> 9;
    int i   = idx & 511;
    int pos = row & (SS - 1);
    float c = g_cos[pos * 512 + i];
    float s = g_sin[pos * 512 + i];
    size_t base = (size_t)row * D3 + 2 * i;
    float2 q = *(float2*)&g_qkv[base];
    float2 k = *(float2*)&g_qkv[base + DD];
    float2 v = *(float2*)&g_qkv[base + 2 * DD];
    __half2 qo = __floats2half2_rn(q.x * c - q.y * s, q.y * c + q.x * s);
    __half2 ko = __floats2half2_rn(k.x * c - k.y * s, k.y * c + k.x * s);
    __half2 vo = __floats2half2_rn(v.x, v.y);
    *(uint32_t*)&g_qkvh[base]          = *(uint32_t*)&qo;
    *(uint32_t*)&g_qkvh[base + DD]     = *(uint32_t*)&ko;
    *(uint32_t*)&g_qkvh[base + 2 * DD] = *(uint32_t*)&vo;
}

// ---------------- pipelined HGEMM (NT): C = A[M,K]*B[N,K]^T + bias ------------
#define GH_ROWB   80
#define GH_TILE   (128 * GH_ROWB)
#define GH_STAGE  (2 * GH_TILE)
#define GH_SMEM   (3 * GH_STAGE)

__global__ void __launch_bounds__(256, 2)
gemm_h(const __half* __restrict__ A, const __half* __restrict__ B,
       const float* __restrict__ bias, float* __restrict__ C,
       int K, int lda, int ldb, int ldc) {
    extern __shared__ __align__(16) char gsm[];
    uint32_t sbase = smem_u32(gsm);
    int tid = threadIdx.x, warp = tid >> 5, lane = tid & 31;
    int g = lane >> 2, t4 = lane & 3;
    int wm = (warp & 1) * 64;
    int wn = (warp >> 1) * 32;

    const __half* Ab = A + (size_t)(blockIdx.y * 128) * lda;
    const __half* Bb = B + (size_t)(blockIdx.x * 128) * ldb;

    int c1 = tid + 256;
    int ar0 = tid >> 2, ak0 = (tid & 3) * 8;
    int ar1 = c1  >> 2, ak1 = (c1  & 3) * 8;

    uint32_t aOff[4], bOff[4];
    #pragma unroll
    for (int mt = 0; mt < 4; mt++)
        aOff[mt] = (uint32_t)((wm + mt * 16 + (lane & 15)) * GH_ROWB + (lane >> 4) * 16);
    #pragma unroll
    for (int nt = 0; nt < 4; nt++)
        bOff[nt] = (uint32_t)((wn + nt * 8 + (lane & 7)) * GH_ROWB + ((lane >> 3) & 1) * 16)
                 + GH_TILE;

    float acc[4][4][4];
    #pragma unroll
    for (int mt = 0; mt < 4; mt++)
        #pragma unroll
        for (int nt = 0; nt < 4; nt++)
            #pragma unroll
            for (int r = 0; r < 4; r++) acc[mt][nt][r] = 0.f;

    int nk = K >> 5;

    #pragma unroll
    for (int p = 0; p < 2; p++) {
        int k0 = p * 32;
        uint32_t st = sbase + p * GH_STAGE;
        cp16(st + ar0 * GH_ROWB + ak0 * 2,           Ab + (size_t)ar0 * lda + k0 + ak0);
        cp16(st + ar1 * GH_ROWB + ak1 * 2,           Ab + (size_t)ar1 * lda + k0 + ak1);
        cp16(st + GH_TILE + ar0 * GH_ROWB + ak0 * 2, Bb + (size_t)ar0 * ldb + k0 + ak0);
        cp16(st + GH_TILE + ar1 * GH_ROWB + ak1 * 2, Bb + (size_t)ar1 * ldb + k0 + ak1);
        cp_commit();
    }

    for (int it = 0; it < nk; it++) {
        cp_wait<1>();
        __syncthreads();

        if (it + 2 < nk) {
            int k0 = (it + 2) * 32;
            uint32_t st = sbase + ((it + 2) % 3) * GH_STAGE;
            cp16(st + ar0 * GH_ROWB + ak0 * 2,           Ab + (size_t)ar0 * lda + k0 + ak0);
            cp16(st + ar1 * GH_ROWB + ak1 * 2,           Ab + (size_t)ar1 * lda + k0 + ak1);
            cp16(st + GH_TILE + ar0 * GH_ROWB + ak0 * 2, Bb + (size_t)ar0 * ldb + k0 + ak0);
            cp16(st + GH_TILE + ar1 * GH_ROWB + ak1 * 2, Bb + (size_t)ar1 * ldb + k0 + ak1);
        }
        cp_commit();

        uint32_t sa = sbase + (it % 3) * GH_STAGE;
        #pragma unroll
        for (int ks = 0; ks < 2; ks++) {
            uint32_t af[4][4], bf[4][2];
            #pragma unroll
            for (int mt = 0; mt < 4; mt++) LDSM4(af[mt], sa + aOff[mt] + ks * 32);
            #pragma unroll
            for (int nt = 0; nt < 4; nt++) LDSM2(bf[nt], sa + bOff[nt] + ks * 32);
            #pragma unroll
            for (int mt = 0; mt < 4; mt++)
                #pragma unroll
                for (int nt = 0; nt < 4; nt++)
                    mma_fp16(acc[mt][nt], af[mt], bf[nt]);
        }
    }

    #pragma unroll
    for (int mt = 0; mt < 4; mt++) {
        int row = blockIdx.y * 128 + wm + mt * 16 + g;
        #pragma unroll
        for (int nt = 0; nt < 4; nt++) {
            int col = blockIdx.x * 128 + wn + nt * 8 + 2 * t4;
            float b0 = bias[col], b1 = bias[col + 1];
            float2 o0 = make_float2(acc[mt][nt][0] + b0, acc[mt][nt][1] + b1);
            float2 o1 = make_float2(acc[mt][nt][2] + b0, acc[mt][nt][3] + b1);
            *(float2*)&C[(size_t)row * ldc + col]       = o0;
            *(float2*)&C[(size_t)(row + 8) * ldc + col] = o1;
        }
    }
}

// ---------------- Tensor-core flash attention --------------------------------
// 128 Q-rows per CTA (8 warps x m16), KV tiles of 64, head_dim 64.
// S = Qhi*Khi + Qhi*Klo + Qlo*Khi  (fp32 acc)  -> fp32 softmax in regs
// O = P*Vhi + P*Vlo                (P fp16; only new rounding)
#define AROW 72                    // halfs per smem row (144 B)
#define AQ_HI 0
#define AQ_LO (128*AROW)
#define AK_HI (2*128*AROW)
#define AK_LO (AK_HI + 64*AROW)
#define AV_HI (AK_HI + 2*64*AROW)
#define AV_LO (AK_HI + 3*64*AROW)
#define ATT_SMEM ((2*128*AROW + 4*64*AROW) * 2)

__global__ void __launch_bounds__(256, 2) attn_kernel(const float* __restrict__ mask) {
    extern __shared__ __align__(16) __half asm_[];
    uint32_t sb = smem_u32(asm_);
    int q0 = blockIdx.x * 128;
    int h  = blockIdx.y;
    int b  = blockIdx.z;
    int tid = threadIdx.x, warp = tid >> 5, lane = tid & 31;
    int g = lane >> 2, t4 = lane & 3;

    const float* qg = g_qh + ((size_t)(b * SS + q0)) * DD + h * HD;
    const float* kg = g_kh + ((size_t)b * SS) * DD + h * HD;
    const float* vg = g_vh + ((size_t)b * SS) * DD + h * HD;
    const float* mrow0 = mask + ((size_t)(b * SS + q0 + warp * 16 + g)) * SS;
    const float* mrow1 = mrow0 + 8 * SS;

    // stage Q (128 x 64) hi/lo
    for (int i = tid; i < 4096; i += 256) {         // float2 slots
        int row = i >> 5, c2 = (i & 31) * 2;
        float2 v = *(const float2*)(qg + (size_t)row * DD + c2);
        uint32_t hi, lo;
        split2(v, hi, lo);
        *(uint32_t*)&asm_[AQ_HI + row * AROW + c2] = hi;
        *(uint32_t*)&asm_[AQ_LO + row * AROW + c2] = lo;
    }
    __syncthreads();

    // persistent Q-hi fragments; Q-lo loaded per use
    uint32_t qhi[4][4];
    uint32_t qbase = sb + (uint32_t)((warp * 16 + (lane & 15)) * AROW * 2 + (lane >> 4) * 16);
    #pragma unroll
    for (int ks = 0; ks < 4; ks++) LDSM4(qhi[ks], qbase + ks * 32);

    float m0 = -1e30f, m1 = -1e30f, l0 = 0.f, l1 = 0.f;
    float oacc[8][4];
    #pragma unroll
    for (int nt = 0; nt < 8; nt++)
        #pragma unroll
        for (int r = 0; r < 4; r++) oacc[nt][r] = 0.f;

    uint32_t kfb = sb + (uint32_t)((lane & 7) * AROW * 2 + ((lane >> 3) & 1) * 16);
    uint32_t vfb = sb + (uint32_t)((lane & 15) * AROW * 2);

    for (int j0 = 0; j0 < SS; j0 += 64) {
        __syncthreads();
        // stage K,V (64 x 64 each) hi/lo
        for (int i = tid; i < 2048; i += 256) {
            int row = i >> 5, c2 = (i & 31) * 2;
            float2 kv = *(const float2*)(kg + (size_t)(j0 + row) * DD + c2);
            uint32_t hi, lo;
            split2(kv, hi, lo);
            *(uint32_t*)&asm_[AK_HI + row * AROW + c2] = hi;
            *(uint32_t*)&asm_[AK_LO + row * AROW + c2] = lo;
            float2 vv = *(const float2*)(vg + (size_t)(j0 + row) * DD + c2);
            split2(vv, hi, lo);
            *(uint32_t*)&asm_[AV_HI + row * AROW + c2] = hi;
            *(uint32_t*)&asm_[AV_LO + row * AROW + c2] = lo;
        }
        __syncthreads();

        // S = Q K^T  (3-term)
        float sacc[8][4];
        #pragma unroll
        for (int nt = 0; nt < 8; nt++)
            #pragma unroll
            for (int r = 0; r < 4; r++) sacc[nt][r] = 0.f;

        #pragma unroll
        for (int ks = 0; ks < 4; ks++) {
            uint32_t qlo[4];
            LDSM4(qlo, qbase + AQ_LO * 2 + ks * 32);
            #pragma unroll
            for (int nt = 0; nt < 8; nt++) {
                uint32_t khi[2], klo[2];
                uint32_t ka = kfb + (uint32_t)(nt * 8 * AROW * 2) + ks * 32;
                LDSM2(khi, ka + AK_HI * 2);
                LDSM2(klo, ka + AK_LO * 2);
                mma_fp16(sacc[nt], qhi[ks], khi);
                mma_fp16(sacc[nt], qlo,     khi);
                mma_fp16(sacc[nt], qhi[ks], klo);
            }
        }

        // scale + mask
        const float scl = 0.125f;
        #pragma unroll
        for (int nt = 0; nt < 8; nt++) {
            int col = j0 + nt * 8 + 2 * t4;
            float2 mk0 = *(const float2*)&mrow0[col];
            float2 mk1 = *(const float2*)&mrow1[col];
            sacc[nt][0] = sacc[nt][0] * scl + mk0.x;
            sacc[nt][1] = sacc[nt][1] * scl + mk0.y;
            sacc[nt][2] = sacc[nt][2] * scl + mk1.x;
            sacc[nt][3] = sacc[nt][3] * scl + mk1.y;
        }

        // online softmax (rows g and g+8)
        float rx0 = -1e30f, rx1 = -1e30f;
        #pragma unroll
        for (int nt = 0; nt < 8; nt++) {
            rx0 = fmaxf(rx0, fmaxf(sacc[nt][0], sacc[nt][1]));
            rx1 = fmaxf(rx1, fmaxf(sacc[nt][2], sacc[nt][3]));
        }
        rx0 = fmaxf(rx0, __shfl_xor_sync(0xffffffffu, rx0, 1));
        rx0 = fmaxf(rx0, __shfl_xor_sync(0xffffffffu, rx0, 2));
        rx1 = fmaxf(rx1, __shfl_xor_sync(0xffffffffu, rx1, 1));
        rx1 = fmaxf(rx1, __shfl_xor_sync(0xffffffffu, rx1, 2));
        float mn0 = fmaxf(m0, rx0), mn1 = fmaxf(m1, rx1);
        float rs0 = 0.f, rs1 = 0.f;
        #pragma unroll
        for (int nt = 0; nt < 8; nt++) {
            sacc[nt][0] = __expf(sacc[nt][0] - mn0);
            sacc[nt][1] = __expf(sacc[nt][1] - mn0);
            sacc[nt][2] = __expf(sacc[nt][2] - mn1);
            sacc[nt][3] = __expf(sacc[nt][3] - mn1);
            rs0 += sacc[nt][0] + sacc[nt][1];
            rs1 += sacc[nt][2] + sacc[nt][3];
        }
        rs0 += __shfl_xor_sync(0xffffffffu, rs0, 1);
        rs0 += __shfl_xor_sync(0xffffffffu, rs0, 2);
        rs1 += __shfl_xor_sync(0xffffffffu, rs1, 1);
        rs1 += __shfl_xor_sync(0xffffffffu, rs1, 2);
        float c0 = __expf(m0 - mn0), c1 = __expf(m1 - mn1);
        l0 = l0 * c0 + rs0;  m0 = mn0;
        l1 = l1 * c1 + rs1;  m1 = mn1;
        #pragma unroll
        for (int nt = 0; nt < 8; nt++) {
            oacc[nt][0] *= c0; oacc[nt][1] *= c0;
            oacc[nt][2] *= c1; oacc[nt][3] *= c1;
        }

        // O += P * V   (P fp16 from sacc; V hi + lo)
        #pragma unroll
        for (int kk = 0; kk < 4; kk++) {
            uint32_t pa[4];
            pa[0] = pack_h2(sacc[2*kk  ][0], sacc[2*kk  ][1]);
            pa[1] = pack_h2(sacc[2*kk  ][2], sacc[2*kk  ][3]);
            pa[2] = pack_h2(sacc[2*kk+1][0], sacc[2*kk+1][1]);
            pa[3] = pack_h2(sacc[2*kk+1][2], sacc[2*kk+1][3]);
            #pragma unroll
            for (int nt = 0; nt < 8; nt++) {
                uint32_t vhi[2], vlo[2];
                uint32_t va = vfb + (uint32_t)(kk * 16 * AROW * 2) + nt * 16;
                LDSM2T(vhi, va + AV_HI * 2);
                LDSM2T(vlo, va + AV_LO * 2);
                mma_fp16(oacc[nt], pa, vhi);
                mma_fp16(oacc[nt], pa, vlo);
            }
        }
    }

    // epilogue: O / l -> fp16
    float inv0 = 1.0f / l0, inv1 = 1.0f / l1;
    __half* ob = g_atth + ((size_t)(b * SS + q0 + warp * 16)) * DD + h * HD;
    #pragma unroll
    for (int nt = 0; nt < 8; nt++) {
        int col = nt * 8 + 2 * t4;
        __half2 h0 = __floats2half2_rn(oacc[nt][0] * inv0, oacc[nt][1] * inv0);
        __half2 h1 = __floats2half2_rn(oacc[nt][2] * inv1, oacc[nt][3] * inv1);
        *(uint32_t*)&ob[(size_t)g * DD + col]       = *(uint32_t*)&h0;
        *(uint32_t*)&ob[(size_t)(g + 8) * DD + col] = *(uint32_t*)&h1;
    }
}

// ---------------- launch ------------------------------------------------------
extern "C" void kernel_launch(void* const* d_in, const int* in_sizes, int n_in,
                              void* d_out, int out_size) {
    const float* x     = (const float*)d_in[0];
    const float* mask  = (const float*)d_in[1];
    const float* ln_g  = (const float*)d_in[2];
    const float* ln_b  = (const float*)d_in[3];
    const float* w_qkv = (const float*)d_in[4];
    const float* b_qkv = (const float*)d_in[5];
    const float* in_w  = (const float*)d_in[6];
    const float* in_b  = (const float*)d_in[7];
    const float* out_w = (const float*)d_in[8];
    const float* out_b = (const float*)d_in[9];

    float *qkv, *qh, *kh, *vh;
    __half *xnh, *qkvh, *atth, *wqkvh, *winh, *wouth;
    cudaGetSymbolAddress((void**)&qkv,   g_qkv);
    cudaGetSymbolAddress((void**)&qh,    g_qh);
    cudaGetSymbolAddress((void**)&kh,    g_kh);
    cudaGetSymbolAddress((void**)&vh,    g_vh);
    cudaGetSymbolAddress((void**)&xnh,   g_xnh);
    cudaGetSymbolAddress((void**)&qkvh,  g_qkvh);
    cudaGetSymbolAddress((void**)&atth,  g_atth);
    cudaGetSymbolAddress((void**)&wqkvh, g_wqkvh);
    cudaGetSymbolAddress((void**)&winh,  g_winh);
    cudaGetSymbolAddress((void**)&wouth, g_wouth);

    cudaFuncSetAttribute(attn_kernel,
                         cudaFuncAttributeMaxDynamicSharedMemorySize, ATT_SMEM);
    cudaFuncSetAttribute(gemm_h,
                         cudaFuncAttributeMaxDynamicSharedMemorySize, GH_SMEM);

    // 0. weight conversions
    f2h_kernel<<<(D3*DD/4 + 255)/256, 256>>>(w_qkv, wqkvh, D3*DD/4);
    f2h_kernel<<<(D3*DD/4 + 255)/256, 256>>>(in_w,  winh,  D3*DD/4);
    f2h_kernel<<<(DD*DD/4 + 255)/256, 256>>>(out_w, wouth, DD*DD/4);
    // 1. LayerNorm -> fp16
    ln_kernel<<<BS, 256>>>(x, ln_g, ln_b, xnh);
    // 2. RoPE tables
    rope_table_kernel<<<(SS * (DD/2) + 255) / 256, 256>>>();
    // 3. fused QKV projection
    gemm_h<<<dim3(D3/128, BS/128), 256, GH_SMEM>>>(xnh, wqkvh, b_qkv, qkv,
                                                   DD, DD, DD, D3);
    // 4. RoPE -> fp16 q,k,v
    rope_apply_kernel<<<(BS * (DD/2) + 255) / 256, 256>>>();
    // 5. in-projections
    gemm_h<<<dim3(DD/128, BS/128), 256, GH_SMEM>>>(qkvh,        winh,           in_b,        qh, DD, D3, DD, DD);
    gemm_h<<<dim3(DD/128, BS/128), 256, GH_SMEM>>>(qkvh + DD,   winh + DD*DD,   in_b + DD,   kh, DD, D3, DD, DD);
    gemm_h<<<dim3(DD/128, BS/128), 256, GH_SMEM>>>(qkvh + 2*DD, winh + 2*DD*DD, in_b + 2*DD, vh, DD, D3, DD, DD);
    // 6. tensor-core flash attention -> fp16
    attn_kernel<<<dim3(SS/128, HH, BB), 256, ATT_SMEM>>>(mask);
    // 7. out-projection -> d_out (fp32)
    gemm_h<<<dim3(DD/128, BS/128), 256, GH_SMEM>>>(atth, wouth, out_b, (float*)d_out,
                                                   DD, DD, DD, DD);
}

// round 7
// speedup vs baseline: 3.6624x; 1.5917x over previous
#include <cuda_runtime.h>
#include <cuda_fp16.h>
#include <math.h>
#include <stdint.h>

// Problem constants
#define BB 2
#define SS 2048
#define DD 1024
#define HH 16
#define HD 64
#define BS (BB*SS)          // 4096 rows
#define D3 (3*DD)           // 3072

// ---------------- scratch (device globals; no allocation allowed) ------------
__device__ float  g_qkv [BS*D3];     // fp32 qkv (rope input)
__device__ __half g_xnh [BS*DD];     // fp16 LN output
__device__ __half g_qkvh[BS*D3];     // fp16 post-rope q,k + v (A of in-proj)
__device__ __half g_atth[BS*DD];     // fp16 attention out
__device__ __half g_q_hi[BS*DD], g_q_lo[BS*DD];
__device__ __half g_k_hi[BS*DD], g_k_lo[BS*DD];
__device__ __half g_v_hi[BS*DD], g_v_lo[BS*DD];
__device__ __half g_wqkvh[D3*DD];
__device__ __half g_winh [D3*DD];
__device__ __half g_wouth[DD*DD];
__device__ float  g_cos[SS*(DD/2)];
__device__ float  g_sin[SS*(DD/2)];

// ---------------- ptx helpers -------------------------------------------------
__device__ __forceinline__ uint32_t smem_u32(const void* p) {
    uint32_t a;
    asm("{ .reg .u64 t; cvta.to.shared.u64 t, %1; cvt.u32.u64 %0, t; }"
        : "=r"(a) : "l"(p));
    return a;
}

__device__ __forceinline__ void cp16(uint32_t s, const void* g) {
    asm volatile("cp.async.cg.shared.global [%0], [%1], 16;" :: "r"(s), "l"(g));
}
__device__ __forceinline__ void cp_commit() {
    asm volatile("cp.async.commit_group;" ::: "memory");
}
template <int N>
__device__ __forceinline__ void cp_wait() {
    asm volatile("cp.async.wait_group %0;" :: "n"(N) : "memory");
}

#define LDSM4(r, addr) \
    asm volatile("ldmatrix.sync.aligned.m8n8.x4.shared.b16 {%0,%1,%2,%3}, [%4];" \
        : "=r"((r)[0]), "=r"((r)[1]), "=r"((r)[2]), "=r"((r)[3]) : "r"(addr))
#define LDSM2(r, addr) \
    asm volatile("ldmatrix.sync.aligned.m8n8.x2.shared.b16 {%0,%1}, [%2];" \
        : "=r"((r)[0]), "=r"((r)[1]) : "r"(addr))
#define LDSM2T(r, addr) \
    asm volatile("ldmatrix.sync.aligned.m8n8.x2.trans.shared.b16 {%0,%1}, [%2];" \
        : "=r"((r)[0]), "=r"((r)[1]) : "r"(addr))

__device__ __forceinline__ void mma_fp16(float (&d)[4],
                                         const uint32_t (&a)[4],
                                         const uint32_t (&b)[2]) {
    asm volatile(
        "mma.sync.aligned.m16n8k16.row.col.f32.f16.f16.f32 "
        "{%0,%1,%2,%3}, {%4,%5,%6,%7}, {%8,%9}, {%0,%1,%2,%3};"
        : "+f"(d[0]), "+f"(d[1]), "+f"(d[2]), "+f"(d[3])
        : "r"(a[0]), "r"(a[1]), "r"(a[2]), "r"(a[3]),
          "r"(b[0]), "r"(b[1]));
}

__device__ __forceinline__ uint32_t pack_h2(float x, float y) {
    __half2 h;
    h.x = __float2half_rn(x);
    h.y = __float2half_rn(y);
    return *(uint32_t*)&h;
}

__device__ __forceinline__ void split2(float2 v, uint32_t& hi, uint32_t& lo) {
    __half hx = __float2half_rn(v.x);
    __half hy = __float2half_rn(v.y);
    __half lx = __float2half_rn(v.x - __half2float(hx));
    __half ly = __float2half_rn(v.y - __half2float(hy));
    __half2 h; h.x = hx; h.y = hy;
    __half2 l; l.x = lx; l.y = ly;
    hi = *(uint32_t*)&h;
    lo = *(uint32_t*)&l;
}

// ---------------- fp32 -> fp16 convert ---------------------------------------
__global__ void __launch_bounds__(256) f2h_kernel(const float* __restrict__ src,
                                                  __half* __restrict__ dst, int n4) {
    int i = blockIdx.x * blockDim.x + threadIdx.x;
    if (i >= n4) return;
    float4 v = ((const float4*)src)[i];
    __half2 h0 = __floats2half2_rn(v.x, v.y);
    __half2 h1 = __floats2half2_rn(v.z, v.w);
    *(uint2*)(dst + (size_t)i * 4) = make_uint2(*(uint32_t*)&h0, *(uint32_t*)&h1);
}

// ---------------- LayerNorm -> fp16 -------------------------------------------
__global__ void __launch_bounds__(256) ln_kernel(const float* __restrict__ x,
                                                 const float* __restrict__ g,
                                                 const float* __restrict__ bta,
                                                 __half* __restrict__ outh) {
    int row = blockIdx.x;
    const float4* xr = (const float4*)(x + (size_t)row * DD);
    int t = threadIdx.x;
    float4 v = xr[t];
    float s  = v.x + v.y + v.z + v.w;
    float sq = v.x*v.x + v.y*v.y + v.z*v.z + v.w*v.w;
    #pragma unroll
    for (int off = 16; off; off >>= 1) {
        s  += __shfl_xor_sync(0xffffffffu, s,  off);
        sq += __shfl_xor_sync(0xffffffffu, sq, off);
    }
    __shared__ float red[16];
    int warp = t >> 5, lane = t & 31;
    if (lane == 0) { red[warp] = s; red[8 + warp] = sq; }
    __syncthreads();
    float ts = 0.f, tsq = 0.f;
    #pragma unroll
    for (int w = 0; w < 8; w++) { ts += red[w]; tsq += red[8 + w]; }
    float mu  = ts * (1.0f / DD);
    float var = tsq * (1.0f / DD) - mu * mu;
    float rs  = rsqrtf(var + 1e-5f);
    int col = t * 4;
    float4 gg = *(const float4*)(g   + col);
    float4 bb = *(const float4*)(bta + col);
    __half2 h0 = __floats2half2_rn((v.x - mu) * rs * gg.x + bb.x,
                                   (v.y - mu) * rs * gg.y + bb.y);
    __half2 h1 = __floats2half2_rn((v.z - mu) * rs * gg.z + bb.z,
                                   (v.w - mu) * rs * gg.w + bb.w);
    *(uint2*)(outh + (size_t)row * DD + col) = make_uint2(*(uint32_t*)&h0, *(uint32_t*)&h1);
}

// ---------------- RoPE tables -------------------------------------------------
__global__ void rope_table_kernel() {
    int idx = blockIdx.x * blockDim.x + threadIdx.x;
    if (idx >= SS * (DD/2)) return;
    int pos = idx >> 9;
    int i   = idx & 511;
    double invf = exp(-((double)(2 * i) / (double)DD) * log(10000.0));
    float  ang  = __fmul_rn((float)pos, (float)invf);
    double r    = (double)ang;
    const double TWO_PI = 6.283185307179586476925286766559;
    r -= TWO_PI * rint(r / TWO_PI);
    float rf = (float)r;
    g_cos[idx] = cosf(rf);
    g_sin[idx] = sinf(rf);
}

// ---------------- RoPE apply: fp32 qkv -> fp16 q,k (rotated) + v --------------
__global__ void rope_apply_kernel() {
    int idx = blockIdx.x * blockDim.x + threadIdx.x;
    if (idx >= BS * (DD/2)) return;
    int row = idx >> 9;
    int i   = idx & 511;
    int pos = row & (SS - 1);
    float c = g_cos[pos * 512 + i];
    float s = g_sin[pos * 512 + i];
    size_t base = (size_t)row * D3 + 2 * i;
    float2 q = *(float2*)&g_qkv[base];
    float2 k = *(float2*)&g_qkv[base + DD];
    float2 v = *(float2*)&g_qkv[base + 2 * DD];
    __half2 qo = __floats2half2_rn(q.x * c - q.y * s, q.y * c + q.x * s);
    __half2 ko = __floats2half2_rn(k.x * c - k.y * s, k.y * c + k.x * s);
    __half2 vo = __floats2half2_rn(v.x, v.y);
    *(uint32_t*)&g_qkvh[base]          = *(uint32_t*)&qo;
    *(uint32_t*)&g_qkvh[base + DD]     = *(uint32_t*)&ko;
    *(uint32_t*)&g_qkvh[base + 2 * DD] = *(uint32_t*)&vo;
}

// ---------------- pipelined HGEMM core (shared by both epilogues) -------------
#define GH_ROWB   80
#define GH_TILE   (128 * GH_ROWB)
#define GH_STAGE  (2 * GH_TILE)
#define GH_SMEM   (3 * GH_STAGE)

struct GemmAcc { float a[4][4][4]; };

__device__ __forceinline__ void gemm_core(const __half* __restrict__ A,
                                          const __half* __restrict__ B,
                                          int K, int lda, int ldb,
                                          uint32_t sbase, GemmAcc& AC) {
    int tid = threadIdx.x, warp = tid >> 5, lane = tid & 31;
    int wm = (warp & 1) * 64;
    int wn = (warp >> 1) * 32;

    const __half* Ab = A + (size_t)(blockIdx.y * 128) * lda;
    const __half* Bb = B + (size_t)(blockIdx.x * 128) * ldb;

    int c1 = tid + 256;
    int ar0 = tid >> 2, ak0 = (tid & 3) * 8;
    int ar1 = c1  >> 2, ak1 = (c1  & 3) * 8;

    uint32_t aOff[4], bOff[4];
    #pragma unroll
    for (int mt = 0; mt < 4; mt++)
        aOff[mt] = (uint32_t)((wm + mt * 16 + (lane & 15)) * GH_ROWB + (lane >> 4) * 16);
    #pragma unroll
    for (int nt = 0; nt < 4; nt++)
        bOff[nt] = (uint32_t)((wn + nt * 8 + (lane & 7)) * GH_ROWB + ((lane >> 3) & 1) * 16)
                 + GH_TILE;

    #pragma unroll
    for (int mt = 0; mt < 4; mt++)
        #pragma unroll
        for (int nt = 0; nt < 4; nt++)
            #pragma unroll
            for (int r = 0; r < 4; r++) AC.a[mt][nt][r] = 0.f;

    int nk = K >> 5;

    #pragma unroll
    for (int p = 0; p < 2; p++) {
        int k0 = p * 32;
        uint32_t st = sbase + p * GH_STAGE;
        cp16(st + ar0 * GH_ROWB + ak0 * 2,           Ab + (size_t)ar0 * lda + k0 + ak0);
        cp16(st + ar1 * GH_ROWB + ak1 * 2,           Ab + (size_t)ar1 * lda + k0 + ak1);
        cp16(st + GH_TILE + ar0 * GH_ROWB + ak0 * 2, Bb + (size_t)ar0 * ldb + k0 + ak0);
        cp16(st + GH_TILE + ar1 * GH_ROWB + ak1 * 2, Bb + (size_t)ar1 * ldb + k0 + ak1);
        cp_commit();
    }

    for (int it = 0; it < nk; it++) {
        cp_wait<1>();
        __syncthreads();

        if (it + 2 < nk) {
            int k0 = (it + 2) * 32;
            uint32_t st = sbase + ((it + 2) % 3) * GH_STAGE;
            cp16(st + ar0 * GH_ROWB + ak0 * 2,           Ab + (size_t)ar0 * lda + k0 + ak0);
            cp16(st + ar1 * GH_ROWB + ak1 * 2,           Ab + (size_t)ar1 * lda + k0 + ak1);
            cp16(st + GH_TILE + ar0 * GH_ROWB + ak0 * 2, Bb + (size_t)ar0 * ldb + k0 + ak0);
            cp16(st + GH_TILE + ar1 * GH_ROWB + ak1 * 2, Bb + (size_t)ar1 * ldb + k0 + ak1);
        }
        cp_commit();

        uint32_t sa = sbase + (it % 3) * GH_STAGE;
        #pragma unroll
        for (int ks = 0; ks < 2; ks++) {
            uint32_t af[4][4], bf[4][2];
            #pragma unroll
            for (int mt = 0; mt < 4; mt++) LDSM4(af[mt], sa + aOff[mt] + ks * 32);
            #pragma unroll
            for (int nt = 0; nt < 4; nt++) LDSM2(bf[nt], sa + bOff[nt] + ks * 32);
            #pragma unroll
            for (int mt = 0; mt < 4; mt++)
                #pragma unroll
                for (int nt = 0; nt < 4; nt++)
                    mma_fp16(AC.a[mt][nt], af[mt], bf[nt]);
        }
    }
}

// fp32 epilogue
__global__ void __launch_bounds__(256, 2)
gemm_h(const __half* __restrict__ A, const __half* __restrict__ B,
       const float* __restrict__ bias, float* __restrict__ C,
       int K, int lda, int ldb, int ldc) {
    extern __shared__ __align__(16) char gsm[];
    GemmAcc AC;
    gemm_core(A, B, K, lda, ldb, smem_u32(gsm), AC);
    int tid = threadIdx.x, warp = tid >> 5, lane = tid & 31;
    int g = lane >> 2, t4 = lane & 3;
    int wm = (warp & 1) * 64, wn = (warp >> 1) * 32;
    #pragma unroll
    for (int mt = 0; mt < 4; mt++) {
        int row = blockIdx.y * 128 + wm + mt * 16 + g;
        #pragma unroll
        for (int nt = 0; nt < 4; nt++) {
            int col = blockIdx.x * 128 + wn + nt * 8 + 2 * t4;
            float b0 = bias[col], b1 = bias[col + 1];
            float2 o0 = make_float2(AC.a[mt][nt][0] + b0, AC.a[mt][nt][1] + b1);
            float2 o1 = make_float2(AC.a[mt][nt][2] + b0, AC.a[mt][nt][3] + b1);
            *(float2*)&C[(size_t)row * ldc + col]       = o0;
            *(float2*)&C[(size_t)(row + 8) * ldc + col] = o1;
        }
    }
}

// hi/lo fp16 split epilogue (for attention inputs)
__global__ void __launch_bounds__(256, 2)
gemm_h_split(const __half* __restrict__ A, const __half* __restrict__ B,
             const float* __restrict__ bias,
             __half* __restrict__ Chi, __half* __restrict__ Clo,
             int K, int lda, int ldb, int ldc) {
    extern __shared__ __align__(16) char gsm[];
    GemmAcc AC;
    gemm_core(A, B, K, lda, ldb, smem_u32(gsm), AC);
    int tid = threadIdx.x, warp = tid >> 5, lane = tid & 31;
    int g = lane >> 2, t4 = lane & 3;
    int wm = (warp & 1) * 64, wn = (warp >> 1) * 32;
    #pragma unroll
    for (int mt = 0; mt < 4; mt++) {
        int row = blockIdx.y * 128 + wm + mt * 16 + g;
        #pragma unroll
        for (int nt = 0; nt < 4; nt++) {
            int col = blockIdx.x * 128 + wn + nt * 8 + 2 * t4;
            float b0 = bias[col], b1 = bias[col + 1];
            uint32_t hi, lo;
            split2(make_float2(AC.a[mt][nt][0] + b0, AC.a[mt][nt][1] + b1), hi, lo);
            *(uint32_t*)&Chi[(size_t)row * ldc + col] = hi;
            *(uint32_t*)&Clo[(size_t)row * ldc + col] = lo;
            split2(make_float2(AC.a[mt][nt][2] + b0, AC.a[mt][nt][3] + b1), hi, lo);
            *(uint32_t*)&Chi[(size_t)(row + 8) * ldc + col] = hi;
            *(uint32_t*)&Clo[(size_t)(row + 8) * ldc + col] = lo;
        }
    }
}

// ---------------- Tensor-core flash attention (cp.async KV pipeline) ----------
// 128 Q-rows per CTA (8 warps x m16), KV tiles of 64, head_dim 64.
// S = Qhi*Khi + Qhi*Klo + Qlo*Khi ; fp32 softmax ; O = P*Vhi + P*Vlo
#define AROW   72                       // halfs per smem row (144 B)
#define AQ_HI  0
#define AQ_LO  (128*AROW)               // 9216
#define AKV0   (2*128*AROW)             // 18432 (halfs)
#define AKV_ST (4*64*AROW)              // 18432 halfs per stage
#define K_HI_O 0
#define K_LO_O (64*AROW)
#define V_HI_O (2*64*AROW)
#define V_LO_O (3*64*AROW)
#define ATT_SMEM ((AKV0 + 2*AKV_ST) * 2)   // 110592 bytes

__global__ void __launch_bounds__(256, 2) attn_kernel(const float* __restrict__ mask) {
    extern __shared__ __align__(16) __half asm_[];
    uint32_t sb = smem_u32(asm_);
    int q0 = blockIdx.x * 128;
    int h  = blockIdx.y;
    int b  = blockIdx.z;
    int tid = threadIdx.x, warp = tid >> 5, lane = tid & 31;
    int g = lane >> 2, t4 = lane & 3;

    const __half* qhig = g_q_hi + ((size_t)(b * SS + q0)) * DD + h * HD;
    const __half* qlog = g_q_lo + ((size_t)(b * SS + q0)) * DD + h * HD;
    const __half* khig = g_k_hi + ((size_t)b * SS) * DD + h * HD;
    const __half* klog = g_k_lo + ((size_t)b * SS) * DD + h * HD;
    const __half* vhig = g_v_hi + ((size_t)b * SS) * DD + h * HD;
    const __half* vlog = g_v_lo + ((size_t)b * SS) * DD + h * HD;
    const float* mrow0 = mask + ((size_t)(b * SS + q0 + warp * 16 + g)) * SS;
    const float* mrow1 = mrow0 + 8 * SS;

    // stage Q (128 x 64) hi/lo via cp.async: 128 rows x 8 chunks x 2 mats = 2048
    {
        #pragma unroll
        for (int i = 0; i < 4; i++) {
            int c = tid + i * 256;               // 0..1023 per matrix
            int row = c >> 3, ck = (c & 7) * 8;  // halfs
            cp16(sb + (uint32_t)(AQ_HI + row * AROW + ck) * 2, qhig + (size_t)row * DD + ck);
            cp16(sb + (uint32_t)(AQ_LO + row * AROW + ck) * 2, qlog + (size_t)row * DD + ck);
        }
        cp_commit();
    }

    // prologue: KV tile 0 into stage 0
    {
        #pragma unroll
        for (int i = 0; i < 2; i++) {
            int c = tid + i * 256;               // 0..511 per matrix
            int row = c >> 3, ck = (c & 7) * 8;
            uint32_t so = (uint32_t)(AKV0 + row * AROW + ck) * 2;
            cp16(sb + so + K_HI_O * 2, khig + (size_t)row * DD + ck);
            cp16(sb + so + K_LO_O * 2, klog + (size_t)row * DD + ck);
            cp16(sb + so + V_HI_O * 2, vhig + (size_t)row * DD + ck);
            cp16(sb + so + V_LO_O * 2, vlog + (size_t)row * DD + ck);
        }
        cp_commit();
    }

    cp_wait<0>();
    __syncthreads();

    // persistent Q-hi fragments
    uint32_t qhi[4][4];
    uint32_t qbase = sb + (uint32_t)((warp * 16 + (lane & 15)) * AROW * 2 + (lane >> 4) * 16);
    #pragma unroll
    for (int ks = 0; ks < 4; ks++) LDSM4(qhi[ks], qbase + ks * 32);

    float m0 = -1e30f, m1 = -1e30f, l0 = 0.f, l1 = 0.f;
    float oacc[8][4];
    #pragma unroll
    for (int nt = 0; nt < 8; nt++)
        #pragma unroll
        for (int r = 0; r < 4; r++) oacc[nt][r] = 0.f;

    for (int it = 0; it < SS / 64; it++) {
        // issue next tile into alternate stage
        if (it + 1 < SS / 64) {
            int j1 = (it + 1) * 64;
            uint32_t st = (uint32_t)(AKV0 + ((it + 1) & 1) * AKV_ST);
            #pragma unroll
            for (int i = 0; i < 2; i++) {
                int c = tid + i * 256;
                int row = c >> 3, ck = (c & 7) * 8;
                uint32_t so = (st + (uint32_t)(row * AROW + ck)) * 2;
                cp16(sb + so + K_HI_O * 2, khig + (size_t)(j1 + row) * DD + ck);
                cp16(sb + so + K_LO_O * 2, klog + (size_t)(j1 + row) * DD + ck);
                cp16(sb + so + V_HI_O * 2, vhig + (size_t)(j1 + row) * DD + ck);
                cp16(sb + so + V_LO_O * 2, vlog + (size_t)(j1 + row) * DD + ck);
            }
            cp_commit();
        }

        int j0 = it * 64;
        uint32_t stb = sb + (uint32_t)(AKV0 + (it & 1) * AKV_ST) * 2;
        uint32_t kfb = stb + (uint32_t)((lane & 7) * AROW * 2 + ((lane >> 3) & 1) * 16);
        uint32_t vfb = stb + V_HI_O * 2 + (uint32_t)((lane & 15) * AROW * 2);

        // S = Q K^T  (3-term)
        float sacc[8][4];
        #pragma unroll
        for (int nt = 0; nt < 8; nt++)
            #pragma unroll
            for (int r = 0; r < 4; r++) sacc[nt][r] = 0.f;

        #pragma unroll
        for (int ks = 0; ks < 4; ks++) {
            uint32_t qlo[4];
            LDSM4(qlo, qbase + AQ_LO * 2 + ks * 32);
            #pragma unroll
            for (int nt = 0; nt < 8; nt++) {
                uint32_t khi[2], klo[2];
                uint32_t ka = kfb + (uint32_t)(nt * 8 * AROW * 2) + ks * 32;
                LDSM2(khi, ka);
                LDSM2(klo, ka + K_LO_O * 2);
                mma_fp16(sacc[nt], qhi[ks], khi);
                mma_fp16(sacc[nt], qlo,     khi);
                mma_fp16(sacc[nt], qhi[ks], klo);
            }
        }

        // scale + mask
        const float scl = 0.125f;
        #pragma unroll
        for (int nt = 0; nt < 8; nt++) {
            int col = j0 + nt * 8 + 2 * t4;
            float2 mk0 = *(const float2*)&mrow0[col];
            float2 mk1 = *(const float2*)&mrow1[col];
            sacc[nt][0] = sacc[nt][0] * scl + mk0.x;
            sacc[nt][1] = sacc[nt][1] * scl + mk0.y;
            sacc[nt][2] = sacc[nt][2] * scl + mk1.x;
            sacc[nt][3] = sacc[nt][3] * scl + mk1.y;
        }

        // online softmax
        float rx0 = -1e30f, rx1 = -1e30f;
        #pragma unroll
        for (int nt = 0; nt < 8; nt++) {
            rx0 = fmaxf(rx0, fmaxf(sacc[nt][0], sacc[nt][1]));
            rx1 = fmaxf(rx1, fmaxf(sacc[nt][2], sacc[nt][3]));
        }
        rx0 = fmaxf(rx0, __shfl_xor_sync(0xffffffffu, rx0, 1));
        rx0 = fmaxf(rx0, __shfl_xor_sync(0xffffffffu, rx0, 2));
        rx1 = fmaxf(rx1, __shfl_xor_sync(0xffffffffu, rx1, 1));
        rx1 = fmaxf(rx1, __shfl_xor_sync(0xffffffffu, rx1, 2));
        float mn0 = fmaxf(m0, rx0), mn1 = fmaxf(m1, rx1);
        float rs0 = 0.f, rs1 = 0.f;
        #pragma unroll
        for (int nt = 0; nt < 8; nt++) {
            sacc[nt][0] = __expf(sacc[nt][0] - mn0);
            sacc[nt][1] = __expf(sacc[nt][1] - mn0);
            sacc[nt][2] = __expf(sacc[nt][2] - mn1);
            sacc[nt][3] = __expf(sacc[nt][3] - mn1);
            rs0 += sacc[nt][0] + sacc[nt][1];
            rs1 += sacc[nt][2] + sacc[nt][3];
        }
        rs0 += __shfl_xor_sync(0xffffffffu, rs0, 1);
        rs0 += __shfl_xor_sync(0xffffffffu, rs0, 2);
        rs1 += __shfl_xor_sync(0xffffffffu, rs1, 1);
        rs1 += __shfl_xor_sync(0xffffffffu, rs1, 2);
        float c0 = __expf(m0 - mn0), c1 = __expf(m1 - mn1);
        l0 = l0 * c0 + rs0;  m0 = mn0;
        l1 = l1 * c1 + rs1;  m1 = mn1;
        #pragma unroll
        for (int nt = 0; nt < 8; nt++) {
            oacc[nt][0] *= c0; oacc[nt][1] *= c0;
            oacc[nt][2] *= c1; oacc[nt][3] *= c1;
        }

        // O += P * V  (P fp16; V hi + lo)
        #pragma unroll
        for (int kk = 0; kk < 4; kk++) {
            uint32_t pa[4];
            pa[0] = pack_h2(sacc[2*kk  ][0], sacc[2*kk  ][1]);
            pa[1] = pack_h2(sacc[2*kk  ][2], sacc[2*kk  ][3]);
            pa[2] = pack_h2(sacc[2*kk+1][0], sacc[2*kk+1][1]);
            pa[3] = pack_h2(sacc[2*kk+1][2], sacc[2*kk+1][3]);
            #pragma unroll
            for (int nt = 0; nt < 8; nt++) {
                uint32_t vhi[2], vlo[2];
                uint32_t va = vfb + (uint32_t)(kk * 16 * AROW * 2) + nt * 16;
                LDSM2T(vhi, va);
                LDSM2T(vlo, va + (V_LO_O - V_HI_O) * 2);
                mma_fp16(oacc[nt], pa, vhi);
                mma_fp16(oacc[nt], pa, vlo);
            }
        }

        // tile it fully consumed; safe for everyone to overwrite it at it+1
        if (it + 1 < SS / 64) {
            cp_wait<0>();
            __syncthreads();
        }
    }

    // epilogue: O / l -> fp16
    float inv0 = 1.0f / l0, inv1 = 1.0f / l1;
    __half* ob = g_atth + ((size_t)(b * SS + q0 + warp * 16)) * DD + h * HD;
    #pragma unroll
    for (int nt = 0; nt < 8; nt++) {
        int col = nt * 8 + 2 * t4;
        __half2 h0 = __floats2half2_rn(oacc[nt][0] * inv0, oacc[nt][1] * inv0);
        __half2 h1 = __floats2half2_rn(oacc[nt][2] * inv1, oacc[nt][3] * inv1);
        *(uint32_t*)&ob[(size_t)g * DD + col]       = *(uint32_t*)&h0;
        *(uint32_t*)&ob[(size_t)(g + 8) * DD + col] = *(uint32_t*)&h1;
    }
}

// ---------------- launch ------------------------------------------------------
extern "C" void kernel_launch(void* const* d_in, const int* in_sizes, int n_in,
                              void* d_out, int out_size) {
    const float* x     = (const float*)d_in[0];
    const float* mask  = (const float*)d_in[1];
    const float* ln_g  = (const float*)d_in[2];
    const float* ln_b  = (const float*)d_in[3];
    const float* w_qkv = (const float*)d_in[4];
    const float* b_qkv = (const float*)d_in[5];
    const float* in_w  = (const float*)d_in[6];
    const float* in_b  = (const float*)d_in[7];
    const float* out_w = (const float*)d_in[8];
    const float* out_b = (const float*)d_in[9];

    float *qkv;
    __half *xnh, *qkvh, *atth, *wqkvh, *winh, *wouth;
    __half *qhi, *qlo, *khi, *klo, *vhi, *vlo;
    cudaGetSymbolAddress((void**)&qkv,   g_qkv);
    cudaGetSymbolAddress((void**)&xnh,   g_xnh);
    cudaGetSymbolAddress((void**)&qkvh,  g_qkvh);
    cudaGetSymbolAddress((void**)&atth,  g_atth);
    cudaGetSymbolAddress((void**)&wqkvh, g_wqkvh);
    cudaGetSymbolAddress((void**)&winh,  g_winh);
    cudaGetSymbolAddress((void**)&wouth, g_wouth);
    cudaGetSymbolAddress((void**)&qhi,   g_q_hi);
    cudaGetSymbolAddress((void**)&qlo,   g_q_lo);
    cudaGetSymbolAddress((void**)&khi,   g_k_hi);
    cudaGetSymbolAddress((void**)&klo,   g_k_lo);
    cudaGetSymbolAddress((void**)&vhi,   g_v_hi);
    cudaGetSymbolAddress((void**)&vlo,   g_v_lo);

    cudaFuncSetAttribute(attn_kernel,
                         cudaFuncAttributeMaxDynamicSharedMemorySize, ATT_SMEM);
    cudaFuncSetAttribute(gemm_h,
                         cudaFuncAttributeMaxDynamicSharedMemorySize, GH_SMEM);
    cudaFuncSetAttribute(gemm_h_split,
                         cudaFuncAttributeMaxDynamicSharedMemorySize, GH_SMEM);

    // 0. weight conversions
    f2h_kernel<<<(D3*DD/4 + 255)/256, 256>>>(w_qkv, wqkvh, D3*DD/4);
    f2h_kernel<<<(D3*DD/4 + 255)/256, 256>>>(in_w,  winh,  D3*DD/4);
    f2h_kernel<<<(DD*DD/4 + 255)/256, 256>>>(out_w, wouth, DD*DD/4);
    // 1. LayerNorm -> fp16
    ln_kernel<<<BS, 256>>>(x, ln_g, ln_b, xnh);
    // 2. RoPE tables
    rope_table_kernel<<<(SS * (DD/2) + 255) / 256, 256>>>();
    // 3. fused QKV projection
    gemm_h<<<dim3(D3/128, BS/128), 256, GH_SMEM>>>(xnh, wqkvh, b_qkv, qkv,
                                                   DD, DD, DD, D3);
    // 4. RoPE -> fp16 q,k,v
    rope_apply_kernel<<<(BS * (DD/2) + 255) / 256, 256>>>();
    // 5. in-projections -> hi/lo fp16 directly
    gemm_h_split<<<dim3(DD/128, BS/128), 256, GH_SMEM>>>(qkvh,        winh,           in_b,        qhi, qlo, DD, D3, DD, DD);
    gemm_h_split<<<dim3(DD/128, BS/128), 256, GH_SMEM>>>(qkvh + DD,   winh + DD*DD,   in_b + DD,   khi, klo, DD, D3, DD, DD);
    gemm_h_split<<<dim3(DD/128, BS/128), 256, GH_SMEM>>>(qkvh + 2*DD, winh + 2*DD*DD, in_b + 2*DD, vhi, vlo, DD, D3, DD, DD);
    // 6. tensor-core flash attention (cp.async KV pipeline) -> fp16
    attn_kernel<<<dim3(SS/128, HH, BB), 256, ATT_SMEM>>>(mask);
    // 7. out-projection -> d_out (fp32)
    gemm_h<<<dim3(DD/128, BS/128), 256, GH_SMEM>>>(atth, wouth, out_b, (float*)d_out,
                                                   DD, DD, DD, DD);
}

// round 8
// speedup vs baseline: 3.8054x; 1.0390x over previous
#include <cuda_runtime.h>
#include <cuda_fp16.h>
#include <math.h>
#include <stdint.h>

// Problem constants
#define BB 2
#define SS 2048
#define DD 1024
#define HH 16
#define HD 64
#define BS (BB*SS)          // 4096 rows
#define D3 (3*DD)           // 3072

// ---------------- scratch (device globals; no allocation allowed) ------------
__device__ __half g_xnh [BS*DD];     // fp16 LN output
__device__ __half g_qkvh[BS*D3];     // fp16 post-rope q,k + v (A of in-proj)
__device__ __half g_atth[BS*DD];     // fp16 attention out
__device__ __half g_q_hi[BS*DD], g_q_lo[BS*DD];
__device__ __half g_k_hi[BS*DD], g_k_lo[BS*DD];
__device__ __half g_v_hi[BS*DD], g_v_lo[BS*DD];
__device__ __half g_wqkvh[D3*DD];
__device__ __half g_winh [D3*DD];
__device__ __half g_wouth[DD*DD];
__device__ float  g_cos[SS*(DD/2)];
__device__ float  g_sin[SS*(DD/2)];

// ---------------- ptx helpers -------------------------------------------------
__device__ __forceinline__ uint32_t smem_u32(const void* p) {
    uint32_t a;
    asm("{ .reg .u64 t; cvta.to.shared.u64 t, %1; cvt.u32.u64 %0, t; }"
        : "=r"(a) : "l"(p));
    return a;
}

__device__ __forceinline__ void cp16(uint32_t s, const void* g) {
    asm volatile("cp.async.cg.shared.global [%0], [%1], 16;" :: "r"(s), "l"(g));
}
__device__ __forceinline__ void cp_commit() {
    asm volatile("cp.async.commit_group;" ::: "memory");
}
template <int N>
__device__ __forceinline__ void cp_wait() {
    asm volatile("cp.async.wait_group %0;" :: "n"(N) : "memory");
}

#define LDSM4(r, addr) \
    asm volatile("ldmatrix.sync.aligned.m8n8.x4.shared.b16 {%0,%1,%2,%3}, [%4];" \
        : "=r"((r)[0]), "=r"((r)[1]), "=r"((r)[2]), "=r"((r)[3]) : "r"(addr))
#define LDSM2(r, addr) \
    asm volatile("ldmatrix.sync.aligned.m8n8.x2.shared.b16 {%0,%1}, [%2];" \
        : "=r"((r)[0]), "=r"((r)[1]) : "r"(addr))
#define LDSM2T(r, addr) \
    asm volatile("ldmatrix.sync.aligned.m8n8.x2.trans.shared.b16 {%0,%1}, [%2];" \
        : "=r"((r)[0]), "=r"((r)[1]) : "r"(addr))

__device__ __forceinline__ void mma_fp16(float (&d)[4],
                                         const uint32_t (&a)[4],
                                         const uint32_t (&b)[2]) {
    asm volatile(
        "mma.sync.aligned.m16n8k16.row.col.f32.f16.f16.f32 "
        "{%0,%1,%2,%3}, {%4,%5,%6,%7}, {%8,%9}, {%0,%1,%2,%3};"
        : "+f"(d[0]), "+f"(d[1]), "+f"(d[2]), "+f"(d[3])
        : "r"(a[0]), "r"(a[1]), "r"(a[2]), "r"(a[3]),
          "r"(b[0]), "r"(b[1]));
}

__device__ __forceinline__ uint32_t pack_h2(float x, float y) {
    __half2 h;
    h.x = __float2half_rn(x);
    h.y = __float2half_rn(y);
    return *(uint32_t*)&h;
}

__device__ __forceinline__ void split2(float2 v, uint32_t& hi, uint32_t& lo) {
    __half hx = __float2half_rn(v.x);
    __half hy = __float2half_rn(v.y);
    __half lx = __float2half_rn(v.x - __half2float(hx));
    __half ly = __float2half_rn(v.y - __half2float(hy));
    __half2 h; h.x = hx; h.y = hy;
    __half2 l; l.x = lx; l.y = ly;
    hi = *(uint32_t*)&h;
    lo = *(uint32_t*)&l;
}

// ---------------- fused fp32 -> fp16 weight conversion ------------------------
__global__ void __launch_bounds__(256) f2h_all(const float* __restrict__ w1,
                                               const float* __restrict__ w2,
                                               const float* __restrict__ w3) {
    const int s1 = D3*DD/4, s2 = 2*(D3*DD/4), s3 = 2*(D3*DD/4) + DD*DD/4;
    int i = blockIdx.x * blockDim.x + threadIdx.x;
    if (i >= s3) return;
    const float* src;
    __half* dst;
    int j;
    if (i < s1)      { src = w1; dst = g_wqkvh; j = i; }
    else if (i < s2) { src = w2; dst = g_winh;  j = i - s1; }
    else             { src = w3; dst = g_wouth; j = i - s2; }
    float4 v = ((const float4*)src)[j];
    __half2 h0 = __floats2half2_rn(v.x, v.y);
    __half2 h1 = __floats2half2_rn(v.z, v.w);
    *(uint2*)(dst + (size_t)j * 4) = make_uint2(*(uint32_t*)&h0, *(uint32_t*)&h1);
}

// ---------------- LayerNorm -> fp16 -------------------------------------------
__global__ void __launch_bounds__(256) ln_kernel(const float* __restrict__ x,
                                                 const float* __restrict__ g,
                                                 const float* __restrict__ bta) {
    int row = blockIdx.x;
    const float4* xr = (const float4*)(x + (size_t)row * DD);
    int t = threadIdx.x;
    float4 v = xr[t];
    float s  = v.x + v.y + v.z + v.w;
    float sq = v.x*v.x + v.y*v.y + v.z*v.z + v.w*v.w;
    #pragma unroll
    for (int off = 16; off; off >>= 1) {
        s  += __shfl_xor_sync(0xffffffffu, s,  off);
        sq += __shfl_xor_sync(0xffffffffu, sq, off);
    }
    __shared__ float red[16];
    int warp = t >> 5, lane = t & 31;
    if (lane == 0) { red[warp] = s; red[8 + warp] = sq; }
    __syncthreads();
    float ts = 0.f, tsq = 0.f;
    #pragma unroll
    for (int w = 0; w < 8; w++) { ts += red[w]; tsq += red[8 + w]; }
    float mu  = ts * (1.0f / DD);
    float var = tsq * (1.0f / DD) - mu * mu;
    float rs  = rsqrtf(var + 1e-5f);
    int col = t * 4;
    float4 gg = *(const float4*)(g   + col);
    float4 bb = *(const float4*)(bta + col);
    __half2 h0 = __floats2half2_rn((v.x - mu) * rs * gg.x + bb.x,
                                   (v.y - mu) * rs * gg.y + bb.y);
    __half2 h1 = __floats2half2_rn((v.z - mu) * rs * gg.z + bb.z,
                                   (v.w - mu) * rs * gg.w + bb.w);
    *(uint2*)(g_xnh + (size_t)row * DD + col) = make_uint2(*(uint32_t*)&h0, *(uint32_t*)&h1);
}

// ---------------- RoPE tables -------------------------------------------------
__global__ void rope_table_kernel() {
    int idx = blockIdx.x * blockDim.x + threadIdx.x;
    if (idx >= SS * (DD/2)) return;
    int pos = idx >> 9;
    int i   = idx & 511;
    double invf = exp(-((double)(2 * i) / (double)DD) * log(10000.0));
    float  ang  = __fmul_rn((float)pos, (float)invf);
    double r    = (double)ang;
    const double TWO_PI = 6.283185307179586476925286766559;
    r -= TWO_PI * rint(r / TWO_PI);
    float rf = (float)r;
    g_cos[idx] = cosf(rf);
    g_sin[idx] = sinf(rf);
}

// ---------------- pipelined HGEMM core: BK=64, 2-stage cp.async ---------------
#define GH_ROWB   144                   // bytes per smem row (72 halfs: 64 + pad)
#define GH_TILE   (128 * GH_ROWB)       // 18432 B per operand per stage
#define GH_STAGE  (2 * GH_TILE)         // 36864
#define GH_SMEM   (2 * GH_STAGE)        // 73728

struct GemmAcc { float a[4][4][4]; };

__device__ __forceinline__ void gemm_ld_stage(const __half* __restrict__ Ab, int lda,
                                              const __half* __restrict__ Bb, int ldb,
                                              uint32_t st, int k0, int tid) {
    #pragma unroll
    for (int i = 0; i < 8; i++) {
        int c   = tid + i * 256;          // 0..2047
        int op  = c >> 10;                // 0 = A, 1 = B
        int row = (c & 1023) >> 3;        // 0..127
        int ck  = (c & 7) * 8;            // halfs 0..56
        const __half* src = (op ? Bb + (size_t)row * ldb : Ab + (size_t)row * lda) + k0 + ck;
        cp16(st + (uint32_t)(op * GH_TILE + row * GH_ROWB + ck * 2), src);
    }
}

__device__ __forceinline__ void gemm_core(const __half* __restrict__ A,
                                          const __half* __restrict__ B,
                                          int K, int lda, int ldb,
                                          int mblk, int nblk,
                                          uint32_t sbase, GemmAcc& AC) {
    int tid = threadIdx.x, warp = tid >> 5, lane = tid & 31;
    int wm = (warp & 1) * 64;
    int wn = (warp >> 1) * 32;

    const __half* Ab = A + (size_t)(mblk * 128) * lda;
    const __half* Bb = B + (size_t)(nblk * 128) * ldb;

    uint32_t aOff[4], bOff[4];
    #pragma unroll
    for (int mt = 0; mt < 4; mt++)
        aOff[mt] = (uint32_t)((wm + mt * 16 + (lane & 15)) * GH_ROWB + (lane >> 4) * 16);
    #pragma unroll
    for (int nt = 0; nt < 4; nt++)
        bOff[nt] = (uint32_t)((wn + nt * 8 + (lane & 7)) * GH_ROWB + ((lane >> 3) & 1) * 16)
                 + GH_TILE;

    #pragma unroll
    for (int mt = 0; mt < 4; mt++)
        #pragma unroll
        for (int nt = 0; nt < 4; nt++)
            #pragma unroll
            for (int r = 0; r < 4; r++) AC.a[mt][nt][r] = 0.f;

    int nk = K >> 6;

    gemm_ld_stage(Ab, lda, Bb, ldb, sbase, 0, tid);
    cp_commit();
    cp_wait<0>();
    __syncthreads();

    for (int it = 0; it < nk; it++) {
        if (it + 1 < nk) {
            gemm_ld_stage(Ab, lda, Bb, ldb,
                          sbase + ((it + 1) & 1) * GH_STAGE, (it + 1) << 6, tid);
            cp_commit();
        }

        uint32_t sa = sbase + (it & 1) * GH_STAGE;
        #pragma unroll
        for (int ks = 0; ks < 4; ks++) {
            uint32_t af[4][4], bf[4][2];
            #pragma unroll
            for (int mt = 0; mt < 4; mt++) LDSM4(af[mt], sa + aOff[mt] + ks * 32);
            #pragma unroll
            for (int nt = 0; nt < 4; nt++) LDSM2(bf[nt], sa + bOff[nt] + ks * 32);
            #pragma unroll
            for (int mt = 0; mt < 4; mt++)
                #pragma unroll
                for (int nt = 0; nt < 4; nt++)
                    mma_fp16(AC.a[mt][nt], af[mt], bf[nt]);
        }

        if (it + 1 < nk) {
            cp_wait<0>();
            __syncthreads();
        }
    }
}

// ---- QKV GEMM with fused bias + RoPE epilogue -> fp16 g_qkvh -----------------
__global__ void __launch_bounds__(256, 2)
gemm_qkv_rope(const float* __restrict__ bias) {
    extern __shared__ __align__(16) char gsm[];
    GemmAcc AC;
    gemm_core(g_xnh, g_wqkvh, DD, DD, DD, blockIdx.y, blockIdx.x, smem_u32(gsm), AC);
    int tid = threadIdx.x, warp = tid >> 5, lane = tid & 31;
    int g = lane >> 2, t4 = lane & 3;
    int wm = (warp & 1) * 64, wn = (warp >> 1) * 32;
    int sec = blockIdx.x >> 3;          // 0=q, 1=k, 2=v (128-col blocks align)
    #pragma unroll
    for (int mt = 0; mt < 4; mt++) {
        int row = blockIdx.y * 128 + wm + mt * 16 + g;
        #pragma unroll
        for (int nt = 0; nt < 4; nt++) {
            int col = blockIdx.x * 128 + wn + nt * 8 + 2 * t4;
            float b0 = bias[col], b1 = bias[col + 1];
            float o0 = AC.a[mt][nt][0] + b0, o1 = AC.a[mt][nt][1] + b1;
            float o2 = AC.a[mt][nt][2] + b0, o3 = AC.a[mt][nt][3] + b1;
            if (sec < 2) {
                int i  = (col & 1023) >> 1;
                int p0 = row & (SS - 1);
                int p1 = (row + 8) & (SS - 1);
                float c0 = g_cos[p0 * 512 + i], s0 = g_sin[p0 * 512 + i];
                float c1 = g_cos[p1 * 512 + i], s1 = g_sin[p1 * 512 + i];
                float r0 = o0 * c0 - o1 * s0, r1 = o1 * c0 + o0 * s0;
                float r2 = o2 * c1 - o3 * s1, r3 = o3 * c1 + o2 * s1;
                o0 = r0; o1 = r1; o2 = r2; o3 = r3;
            }
            *(uint32_t*)&g_qkvh[(size_t)row * D3 + col]       = pack_h2(o0, o1);
            *(uint32_t*)&g_qkvh[(size_t)(row + 8) * D3 + col] = pack_h2(o2, o3);
        }
    }
}

// ---- merged in-projections (q,k,v) with hi/lo split epilogue -----------------
__global__ void __launch_bounds__(256, 2)
gemm_inproj(const float* __restrict__ bias_all) {
    extern __shared__ __align__(16) char gsm[];
    int sec = blockIdx.x >> 3, nb = blockIdx.x & 7;
    const __half* A = g_qkvh + sec * DD;
    const __half* B = g_winh + (size_t)sec * DD * DD;
    GemmAcc AC;
    gemm_core(A, B, DD, D3, DD, blockIdx.y, nb, smem_u32(gsm), AC);
    const float* bias = bias_all + sec * DD;
    __half *Chi, *Clo;
    if (sec == 0)      { Chi = g_q_hi; Clo = g_q_lo; }
    else if (sec == 1) { Chi = g_k_hi; Clo = g_k_lo; }
    else               { Chi = g_v_hi; Clo = g_v_lo; }
    int tid = threadIdx.x, warp = tid >> 5, lane = tid & 31;
    int g = lane >> 2, t4 = lane & 3;
    int wm = (warp & 1) * 64, wn = (warp >> 1) * 32;
    #pragma unroll
    for (int mt = 0; mt < 4; mt++) {
        int row = blockIdx.y * 128 + wm + mt * 16 + g;
        #pragma unroll
        for (int nt = 0; nt < 4; nt++) {
            int col = nb * 128 + wn + nt * 8 + 2 * t4;
            float b0 = bias[col], b1 = bias[col + 1];
            uint32_t hi, lo;
            split2(make_float2(AC.a[mt][nt][0] + b0, AC.a[mt][nt][1] + b1), hi, lo);
            *(uint32_t*)&Chi[(size_t)row * DD + col] = hi;
            *(uint32_t*)&Clo[(size_t)row * DD + col] = lo;
            split2(make_float2(AC.a[mt][nt][2] + b0, AC.a[mt][nt][3] + b1), hi, lo);
            *(uint32_t*)&Chi[(size_t)(row + 8) * DD + col] = hi;
            *(uint32_t*)&Clo[(size_t)(row + 8) * DD + col] = lo;
        }
    }
}

// ---- out-projection: fp32 epilogue -------------------------------------------
__global__ void __launch_bounds__(256, 2)
gemm_out(const float* __restrict__ bias, float* __restrict__ C) {
    extern __shared__ __align__(16) char gsm[];
    GemmAcc AC;
    gemm_core(g_atth, g_wouth, DD, DD, DD, blockIdx.y, blockIdx.x, smem_u32(gsm), AC);
    int tid = threadIdx.x, warp = tid >> 5, lane = tid & 31;
    int g = lane >> 2, t4 = lane & 3;
    int wm = (warp & 1) * 64, wn = (warp >> 1) * 32;
    #pragma unroll
    for (int mt = 0; mt < 4; mt++) {
        int row = blockIdx.y * 128 + wm + mt * 16 + g;
        #pragma unroll
        for (int nt = 0; nt < 4; nt++) {
            int col = blockIdx.x * 128 + wn + nt * 8 + 2 * t4;
            float b0 = bias[col], b1 = bias[col + 1];
            float2 o0 = make_float2(AC.a[mt][nt][0] + b0, AC.a[mt][nt][1] + b1);
            float2 o1 = make_float2(AC.a[mt][nt][2] + b0, AC.a[mt][nt][3] + b1);
            *(float2*)&C[(size_t)row * DD + col]       = o0;
            *(float2*)&C[(size_t)(row + 8) * DD + col] = o1;
        }
    }
}

// ---------------- Tensor-core flash attention (cp.async KV pipeline) ----------
#define AROW   72
#define AQ_HI  0
#define AQ_LO  (128*AROW)
#define AKV0   (2*128*AROW)
#define AKV_ST (4*64*AROW)
#define K_HI_O 0
#define K_LO_O (64*AROW)
#define V_HI_O (2*64*AROW)
#define V_LO_O (3*64*AROW)
#define ATT_SMEM ((AKV0 + 2*AKV_ST) * 2)   // 110592 bytes

__global__ void __launch_bounds__(256, 2) attn_kernel(const float* __restrict__ mask) {
    extern __shared__ __align__(16) __half asm_[];
    uint32_t sb = smem_u32(asm_);
    int q0 = blockIdx.x * 128;
    int h  = blockIdx.y;
    int b  = blockIdx.z;
    int tid = threadIdx.x, warp = tid >> 5, lane = tid & 31;
    int g = lane >> 2, t4 = lane & 3;

    const __half* qhig = g_q_hi + ((size_t)(b * SS + q0)) * DD + h * HD;
    const __half* qlog = g_q_lo + ((size_t)(b * SS + q0)) * DD + h * HD;
    const __half* khig = g_k_hi + ((size_t)b * SS) * DD + h * HD;
    const __half* klog = g_k_lo + ((size_t)b * SS) * DD + h * HD;
    const __half* vhig = g_v_hi + ((size_t)b * SS) * DD + h * HD;
    const __half* vlog = g_v_lo + ((size_t)b * SS) * DD + h * HD;
    const float* mrow0 = mask + ((size_t)(b * SS + q0 + warp * 16 + g)) * SS;
    const float* mrow1 = mrow0 + 8 * SS;

    {
        #pragma unroll
        for (int i = 0; i < 4; i++) {
            int c = tid + i * 256;
            int row = c >> 3, ck = (c & 7) * 8;
            cp16(sb + (uint32_t)(AQ_HI + row * AROW + ck) * 2, qhig + (size_t)row * DD + ck);
            cp16(sb + (uint32_t)(AQ_LO + row * AROW + ck) * 2, qlog + (size_t)row * DD + ck);
        }
        cp_commit();
    }
    {
        #pragma unroll
        for (int i = 0; i < 2; i++) {
            int c = tid + i * 256;
            int row = c >> 3, ck = (c & 7) * 8;
            uint32_t so = (uint32_t)(AKV0 + row * AROW + ck) * 2;
            cp16(sb + so + K_HI_O * 2, khig + (size_t)row * DD + ck);
            cp16(sb + so + K_LO_O * 2, klog + (size_t)row * DD + ck);
            cp16(sb + so + V_HI_O * 2, vhig + (size_t)row * DD + ck);
            cp16(sb + so + V_LO_O * 2, vlog + (size_t)row * DD + ck);
        }
        cp_commit();
    }

    cp_wait<0>();
    __syncthreads();

    uint32_t qhi[4][4];
    uint32_t qbase = sb + (uint32_t)((warp * 16 + (lane & 15)) * AROW * 2 + (lane >> 4) * 16);
    #pragma unroll
    for (int ks = 0; ks < 4; ks++) LDSM4(qhi[ks], qbase + ks * 32);

    float m0 = -1e30f, m1 = -1e30f, l0 = 0.f, l1 = 0.f;
    float oacc[8][4];
    #pragma unroll
    for (int nt = 0; nt < 8; nt++)
        #pragma unroll
        for (int r = 0; r < 4; r++) oacc[nt][r] = 0.f;

    for (int it = 0; it < SS / 64; it++) {
        if (it + 1 < SS / 64) {
            int j1 = (it + 1) * 64;
            uint32_t st = (uint32_t)(AKV0 + ((it + 1) & 1) * AKV_ST);
            #pragma unroll
            for (int i = 0; i < 2; i++) {
                int c = tid + i * 256;
                int row = c >> 3, ck = (c & 7) * 8;
                uint32_t so = (st + (uint32_t)(row * AROW + ck)) * 2;
                cp16(sb + so + K_HI_O * 2, khig + (size_t)(j1 + row) * DD + ck);
                cp16(sb + so + K_LO_O * 2, klog + (size_t)(j1 + row) * DD + ck);
                cp16(sb + so + V_HI_O * 2, vhig + (size_t)(j1 + row) * DD + ck);
                cp16(sb + so + V_LO_O * 2, vlog + (size_t)(j1 + row) * DD + ck);
            }
            cp_commit();
        }

        int j0 = it * 64;
        uint32_t stb = sb + (uint32_t)(AKV0 + (it & 1) * AKV_ST) * 2;
        uint32_t kfb = stb + (uint32_t)((lane & 7) * AROW * 2 + ((lane >> 3) & 1) * 16);
        uint32_t vfb = stb + V_HI_O * 2 + (uint32_t)((lane & 15) * AROW * 2);

        float sacc[8][4];
        #pragma unroll
        for (int nt = 0; nt < 8; nt++)
            #pragma unroll
            for (int r = 0; r < 4; r++) sacc[nt][r] = 0.f;

        #pragma unroll
        for (int ks = 0; ks < 4; ks++) {
            uint32_t qlo[4];
            LDSM4(qlo, qbase + AQ_LO * 2 + ks * 32);
            #pragma unroll
            for (int nt = 0; nt < 8; nt++) {
                uint32_t khi[2], klo[2];
                uint32_t ka = kfb + (uint32_t)(nt * 8 * AROW * 2) + ks * 32;
                LDSM2(khi, ka);
                LDSM2(klo, ka + K_LO_O * 2);
                mma_fp16(sacc[nt], qhi[ks], khi);
                mma_fp16(sacc[nt], qlo,     khi);
                mma_fp16(sacc[nt], qhi[ks], klo);
            }
        }

        const float scl = 0.125f;
        #pragma unroll
        for (int nt = 0; nt < 8; nt++) {
            int col = j0 + nt * 8 + 2 * t4;
            float2 mk0 = *(const float2*)&mrow0[col];
            float2 mk1 = *(const float2*)&mrow1[col];
            sacc[nt][0] = sacc[nt][0] * scl + mk0.x;
            sacc[nt][1] = sacc[nt][1] * scl + mk0.y;
            sacc[nt][2] = sacc[nt][2] * scl + mk1.x;
            sacc[nt][3] = sacc[nt][3] * scl + mk1.y;
        }

        float rx0 = -1e30f, rx1 = -1e30f;
        #pragma unroll
        for (int nt = 0; nt < 8; nt++) {
            rx0 = fmaxf(rx0, fmaxf(sacc[nt][0], sacc[nt][1]));
            rx1 = fmaxf(rx1, fmaxf(sacc[nt][2], sacc[nt][3]));
        }
        rx0 = fmaxf(rx0, __shfl_xor_sync(0xffffffffu, rx0, 1));
        rx0 = fmaxf(rx0, __shfl_xor_sync(0xffffffffu, rx0, 2));
        rx1 = fmaxf(rx1, __shfl_xor_sync(0xffffffffu, rx1, 1));
        rx1 = fmaxf(rx1, __shfl_xor_sync(0xffffffffu, rx1, 2));
        float mn0 = fmaxf(m0, rx0), mn1 = fmaxf(m1, rx1);
        float rs0 = 0.f, rs1 = 0.f;
        #pragma unroll
        for (int nt = 0; nt < 8; nt++) {
            sacc[nt][0] = __expf(sacc[nt][0] - mn0);
            sacc[nt][1] = __expf(sacc[nt][1] - mn0);
            sacc[nt][2] = __expf(sacc[nt][2] - mn1);
            sacc[nt][3] = __expf(sacc[nt][3] - mn1);
            rs0 += sacc[nt][0] + sacc[nt][1];
            rs1 += sacc[nt][2] + sacc[nt][3];
        }
        rs0 += __shfl_xor_sync(0xffffffffu, rs0, 1);
        rs0 += __shfl_xor_sync(0xffffffffu, rs0, 2);
        rs1 += __shfl_xor_sync(0xffffffffu, rs1, 1);
        rs1 += __shfl_xor_sync(0xffffffffu, rs1, 2);
        float c0 = __expf(m0 - mn0), c1 = __expf(m1 - mn1);
        l0 = l0 * c0 + rs0;  m0 = mn0;
        l1 = l1 * c1 + rs1;  m1 = mn1;
        #pragma unroll
        for (int nt = 0; nt < 8; nt++) {
            oacc[nt][0] *= c0; oacc[nt][1] *= c0;
            oacc[nt][2] *= c1; oacc[nt][3] *= c1;
        }

        #pragma unroll
        for (int kk = 0; kk < 4; kk++) {
            uint32_t pa[4];
            pa[0] = pack_h2(sacc[2*kk  ][0], sacc[2*kk  ][1]);
            pa[1] = pack_h2(sacc[2*kk  ][2], sacc[2*kk  ][3]);
            pa[2] = pack_h2(sacc[2*kk+1][0], sacc[2*kk+1][1]);
            pa[3] = pack_h2(sacc[2*kk+1][2], sacc[2*kk+1][3]);
            #pragma unroll
            for (int nt = 0; nt < 8; nt++) {
                uint32_t vhi[2], vlo[2];
                uint32_t va = vfb + (uint32_t)(kk * 16 * AROW * 2) + nt * 16;
                LDSM2T(vhi, va);
                LDSM2T(vlo, va + (V_LO_O - V_HI_O) * 2);
                mma_fp16(oacc[nt], pa, vhi);
                mma_fp16(oacc[nt], pa, vlo);
            }
        }

        if (it + 1 < SS / 64) {
            cp_wait<0>();
            __syncthreads();
        }
    }

    float inv0 = 1.0f / l0, inv1 = 1.0f / l1;
    __half* ob = g_atth + ((size_t)(b * SS + q0 + warp * 16)) * DD + h * HD;
    #pragma unroll
    for (int nt = 0; nt < 8; nt++) {
        int col = nt * 8 + 2 * t4;
        __half2 h0 = __floats2half2_rn(oacc[nt][0] * inv0, oacc[nt][1] * inv0);
        __half2 h1 = __floats2half2_rn(oacc[nt][2] * inv1, oacc[nt][3] * inv1);
        *(uint32_t*)&ob[(size_t)g * DD + col]       = *(uint32_t*)&h0;
        *(uint32_t*)&ob[(size_t)(g + 8) * DD + col] = *(uint32_t*)&h1;
    }
}

// ---------------- launch ------------------------------------------------------
extern "C" void kernel_launch(void* const* d_in, const int* in_sizes, int n_in,
                              void* d_out, int out_size) {
    const float* x     = (const float*)d_in[0];
    const float* mask  = (const float*)d_in[1];
    const float* ln_g  = (const float*)d_in[2];
    const float* ln_b  = (const float*)d_in[3];
    const float* w_qkv = (const float*)d_in[4];
    const float* b_qkv = (const float*)d_in[5];
    const float* in_w  = (const float*)d_in[6];
    const float* in_b  = (const float*)d_in[7];
    const float* out_w = (const float*)d_in[8];
    const float* out_b = (const float*)d_in[9];

    cudaFuncSetAttribute(attn_kernel,
                         cudaFuncAttributeMaxDynamicSharedMemorySize, ATT_SMEM);
    cudaFuncSetAttribute(gemm_qkv_rope,
                         cudaFuncAttributeMaxDynamicSharedMemorySize, GH_SMEM);
    cudaFuncSetAttribute(gemm_inproj,
                         cudaFuncAttributeMaxDynamicSharedMemorySize, GH_SMEM);
    cudaFuncSetAttribute(gemm_out,
                         cudaFuncAttributeMaxDynamicSharedMemorySize, GH_SMEM);

    // 0. fused weight conversions (fp32 -> fp16)
    int n4tot = 2 * (D3*DD/4) + DD*DD/4;
    f2h_all<<<(n4tot + 255)/256, 256>>>(w_qkv, in_w, out_w);
    // 1. LayerNorm -> fp16
    ln_kernel<<<BS, 256>>>(x, ln_g, ln_b);
    // 2. RoPE tables (consumed by the QKV epilogue)
    rope_table_kernel<<<(SS * (DD/2) + 255) / 256, 256>>>();
    // 3. fused QKV projection + bias + RoPE -> fp16 g_qkvh
    gemm_qkv_rope<<<dim3(D3/128, BS/128), 256, GH_SMEM>>>(b_qkv);
    // 4. merged in-projections -> hi/lo fp16
    gemm_inproj<<<dim3(D3/128, BS/128), 256, GH_SMEM>>>(in_b);
    // 5. tensor-core flash attention -> fp16
    attn_kernel<<<dim3(SS/128, HH, BB), 256, ATT_SMEM>>>(mask);
    // 6. out-projection -> d_out (fp32)
    gemm_out<<<dim3(DD/128, BS/128), 256, GH_SMEM>>>(out_b, (float*)d_out);
}